// round 6
// baseline (speedup 1.0000x reference)
#include <cuda_runtime.h>
#include <math.h>
#include <stdint.h>

#define BB  4
#define SS  2048
#define PP  32
#define DD  512
#define HH  8
#define LL  2
#define DF  2048
#define HD  64
#define MM  (BB*SS)   /* 8192 rows */

// ---------------- scratch (device globals; no allocations allowed) ----------
__device__ float g_h [MM*DD];
__device__ float g_q [MM*DD];
__device__ float g_k [MM*DD];
__device__ float g_v [MM*DD];
__device__ float g_o [MM*DD];
__device__ float g_t [MM*DD];
__device__ float g_ff[MM*DF];
__device__ float g_cos[SS*32];
__device__ float g_sin[SS*32];

// ---------------- RoPE tables ----------------------------------------------
__global__ void rope_tables_kernel(float* __restrict__ ct, float* __restrict__ st) {
    int idx = blockIdx.x * blockDim.x + threadIdx.x;
    if (idx >= SS * 32) return;
    int pos = idx >> 5;
    int i   = idx & 31;
    int fidx = (2 * i) & 31;
    float ex  = (float)(2 * fidx) / 64.0f;
    float inv = 1.0f / powf(10000.0f, ex);
    float ang = (float)pos * inv;
    ct[idx] = cosf(ang);
    st[idx] = sinf(ang);
}

// one launch applies RoPE to both q and k
__global__ void rope_apply_kernel(float* __restrict__ q, float* __restrict__ k,
                                  const float* __restrict__ ct,
                                  const float* __restrict__ st) {
    int gidx = blockIdx.x * blockDim.x + threadIdx.x;   // 2*MM*HH*32 threads
    float* base = (gidx < MM * HH * 32) ? q : k;
    int idx = (gidx < MM * HH * 32) ? gidx : gidx - MM * HH * 32;
    int i   = idx & 31;
    int rem = idx >> 5;
    int hh  = rem & (HH - 1);
    int row = rem >> 3;
    int s   = row & (SS - 1);
    float c  = ct[s * 32 + i];
    float sn = st[s * 32 + i];
    float* p = base + (size_t)row * DD + hh * HD + 2 * i;
    float x1 = p[0], x2 = p[1];
    p[0] = x1 * c - x2 * sn;
    p[1] = x1 * sn + x2 * c;
}

// ---------------- tf32 helpers ----------------------------------------------
__device__ __forceinline__ uint32_t f2tf(float f) {
    uint32_t u;
    asm("cvt.rna.tf32.f32 %0, %1;" : "=r"(u) : "f"(f));
    return u;
}

__device__ __forceinline__ void mma_tf32(float* c, const uint32_t* a, const uint32_t* b) {
    asm volatile(
        "mma.sync.aligned.m16n8k8.row.col.f32.tf32.tf32.f32 "
        "{%0,%1,%2,%3}, {%4,%5,%6,%7}, {%8,%9}, {%0,%1,%2,%3};\n"
        : "+f"(c[0]), "+f"(c[1]), "+f"(c[2]), "+f"(c[3])
        : "r"(a[0]), "r"(a[1]), "r"(a[2]), "r"(a[3]), "r"(b[0]), "r"(b[1]));
}

// ---------------- TF32 tensor-core GEMM, 64x64 warp tiles --------------------
// C = A[MxK] @ Bsel[KxN] + bias_sel, optional GELU.
// Block 128x128x16, 4 warps (2x2), warp tile 64x64, 2 CTAs/SM, double-buffered.
#define AS_STRIDE 20
#define BS_STRIDE 136

template <int GELU>
__global__ void __launch_bounds__(128, 2)
tgemm_bias(const float* __restrict__ A,
           const float* __restrict__ B0, const float* __restrict__ B1,
           const float* __restrict__ B2,
           const float* __restrict__ bias0, const float* __restrict__ bias1,
           const float* __restrict__ bias2,
           float* __restrict__ C0, float* __restrict__ C1, float* __restrict__ C2,
           int M, int N, int K, int ntile) {
    __shared__ uint32_t As[2][128 * AS_STRIDE];
    __shared__ uint32_t Bs[2][16 * BS_STRIDE];

    const int sel = blockIdx.x / ntile;
    const int bx  = blockIdx.x - sel * ntile;
    const int by  = blockIdx.y;
    const float* B    = (sel == 0) ? B0 : (sel == 1) ? B1 : B2;
    const float* bias = (sel == 0) ? bias0 : (sel == 1) ? bias1 : bias2;
    float*       C    = (sel == 0) ? C0 : (sel == 1) ? C1 : C2;

    const int tid  = threadIdx.x;
    const int warp = tid >> 5;
    const int lane = tid & 31;
    const int g    = lane >> 2;
    const int tg   = lane & 3;
    const int wm   = (warp & 1) * 64;
    const int wn   = (warp >> 1) * 64;

    // staging: A one row per thread (16 cols); B four rows of float4 per thread
    const int bRow = tid >> 5;             // 0..3 (+4i)
    const int bCol = lane * 4;             // 0..124

    const float* Ap = A + (size_t)(by * 128 + tid) * K;
    const float* Bp = B + (size_t)bRow * N + bx * 128 + bCol;
    const size_t Bstep4 = (size_t)4 * N;

    float acc[4][8][4];
#pragma unroll
    for (int i = 0; i < 4; i++)
#pragma unroll
        for (int j = 0; j < 8; j++)
#pragma unroll
            for (int r = 0; r < 4; r++) acc[i][j][r] = 0.0f;

    // prefetch stage 0
    float4 aR[4], bR[4];
#pragma unroll
    for (int i = 0; i < 4; i++) aR[i] = *(const float4*)(Ap + 4 * i);
#pragma unroll
    for (int i = 0; i < 4; i++) bR[i] = *(const float4*)(Bp + i * Bstep4);
    Ap += 16;
    Bp += (size_t)16 * N;

    // store stage 0
#pragma unroll
    for (int i = 0; i < 4; i++) {
        *(uint4*)&As[0][tid * AS_STRIDE + 4 * i] =
            make_uint4(f2tf(aR[i].x), f2tf(aR[i].y), f2tf(aR[i].z), f2tf(aR[i].w));
        *(uint4*)&Bs[0][(bRow + 4 * i) * BS_STRIDE + bCol] =
            make_uint4(f2tf(bR[i].x), f2tf(bR[i].y), f2tf(bR[i].z), f2tf(bR[i].w));
    }
    __syncthreads();

    const int nIter = K >> 4;
    for (int it = 0; it < nIter; it++) {
        const int buf = it & 1;
        const bool more = (it + 1 < nIter);

        if (more) {
#pragma unroll
            for (int i = 0; i < 4; i++) aR[i] = *(const float4*)(Ap + 4 * i);
#pragma unroll
            for (int i = 0; i < 4; i++) bR[i] = *(const float4*)(Bp + i * Bstep4);
            Ap += 16;
            Bp += (size_t)16 * N;
        }

#pragma unroll
        for (int ks = 0; ks < 16; ks += 8) {
            uint32_t af[4][4], bf[8][2];
#pragma unroll
            for (int mt = 0; mt < 4; mt++) {
                int m = wm + mt * 16;
                af[mt][0] = As[buf][(m + g)     * AS_STRIDE + ks + tg];
                af[mt][1] = As[buf][(m + g + 8) * AS_STRIDE + ks + tg];
                af[mt][2] = As[buf][(m + g)     * AS_STRIDE + ks + tg + 4];
                af[mt][3] = As[buf][(m + g + 8) * AS_STRIDE + ks + tg + 4];
            }
#pragma unroll
            for (int nt = 0; nt < 8; nt++) {
                int n = wn + nt * 8;
                bf[nt][0] = Bs[buf][(ks + tg)     * BS_STRIDE + n + g];
                bf[nt][1] = Bs[buf][(ks + tg + 4) * BS_STRIDE + n + g];
            }
#pragma unroll
            for (int mt = 0; mt < 4; mt++)
#pragma unroll
                for (int nt = 0; nt < 8; nt++)
                    mma_tf32(acc[mt][nt], af[mt], bf[nt]);
        }

        if (more) {
            int nb = buf ^ 1;
#pragma unroll
            for (int i = 0; i < 4; i++) {
                *(uint4*)&As[nb][tid * AS_STRIDE + 4 * i] =
                    make_uint4(f2tf(aR[i].x), f2tf(aR[i].y), f2tf(aR[i].z), f2tf(aR[i].w));
                *(uint4*)&Bs[nb][(bRow + 4 * i) * BS_STRIDE + bCol] =
                    make_uint4(f2tf(bR[i].x), f2tf(bR[i].y), f2tf(bR[i].z), f2tf(bR[i].w));
            }
            __syncthreads();
        }
    }

    // epilogue
#pragma unroll
    for (int mt = 0; mt < 4; mt++) {
#pragma unroll
        for (int nt = 0; nt < 8; nt++) {
            int row0 = by * 128 + wm + mt * 16 + g;
            int col  = bx * 128 + wn + nt * 8 + 2 * tg;
            float bc0 = bias[col], bc1 = bias[col + 1];
            float v0 = acc[mt][nt][0] + bc0;
            float v1 = acc[mt][nt][1] + bc1;
            float v2 = acc[mt][nt][2] + bc0;
            float v3 = acc[mt][nt][3] + bc1;
            if (GELU) {
                v0 = 0.5f * v0 * (1.0f + erff(v0 * 0.70710678118654752f));
                v1 = 0.5f * v1 * (1.0f + erff(v1 * 0.70710678118654752f));
                v2 = 0.5f * v2 * (1.0f + erff(v2 * 0.70710678118654752f));
                v3 = 0.5f * v3 * (1.0f + erff(v3 * 0.70710678118654752f));
            }
            *(float2*)(C + (size_t)row0 * N + col)       = make_float2(v0, v1);
            *(float2*)(C + (size_t)(row0 + 8) * N + col) = make_float2(v2, v3);
        }
    }
}

// ---------------- naive head GEMM: out[M x 32] = h @ Wh + bh ----------------
__global__ void head_gemm_kernel(const float* __restrict__ h,
                                 const float* __restrict__ Wh,
                                 const float* __restrict__ bh,
                                 float* __restrict__ out) {
    int idx = blockIdx.x * blockDim.x + threadIdx.x;
    int n = idx & (PP - 1);
    int m = idx / PP;
    float acc = bh[n];
    const float* hp = h + (size_t)m * DD;
#pragma unroll 8
    for (int k = 0; k < DD; k++) acc += hp[k] * Wh[k * PP + n];
    out[idx] = acc;
}

// ---------------- residual add + LayerNorm (in-place into h) ----------------
__global__ void add_ln_kernel(float* __restrict__ h, const float* __restrict__ d,
                              const float* __restrict__ g, const float* __restrict__ b) {
    int row = blockIdx.x;
    int t   = threadIdx.x;
    float4 hv = *(float4*)(h + (size_t)row * DD + t * 4);
    float4 dv = *(const float4*)(d + (size_t)row * DD + t * 4);
    float v0 = hv.x + dv.x, v1 = hv.y + dv.y, v2 = hv.z + dv.z, v3 = hv.w + dv.w;
    float s  = v0 + v1 + v2 + v3;
    float s2 = v0 * v0 + v1 * v1 + v2 * v2 + v3 * v3;
#pragma unroll
    for (int off = 16; off; off >>= 1) {
        s  += __shfl_xor_sync(0xFFFFFFFF, s,  off);
        s2 += __shfl_xor_sync(0xFFFFFFFF, s2, off);
    }
    __shared__ float sh[8];
    int w = t >> 5, lane = t & 31;
    if (lane == 0) { sh[w] = s; sh[4 + w] = s2; }
    __syncthreads();
    s  = sh[0] + sh[1] + sh[2] + sh[3];
    s2 = sh[4] + sh[5] + sh[6] + sh[7];
    float mean = s * (1.0f / DD);
    float var  = s2 * (1.0f / DD) - mean * mean;
    float inv  = rsqrtf(var + 1e-5f);
    float4 gv = *(const float4*)(g + t * 4);
    float4 bv = *(const float4*)(b + t * 4);
    float4 o;
    o.x = (v0 - mean) * inv * gv.x + bv.x;
    o.y = (v1 - mean) * inv * gv.y + bv.y;
    o.z = (v2 - mean) * inv * gv.z + bv.z;
    o.w = (v3 - mean) * inv * gv.w + bv.w;
    *(float4*)(h + (size_t)row * DD + t * 4) = o;
}

// ---------------- tf32 tensor-core flash attention ---------------------------
#define ATTN_SMEM_U32 17792
#define QST 68
#define VST 72

__global__ void __launch_bounds__(128)
attn3_kernel(const float* __restrict__ q, const float* __restrict__ k,
             const float* __restrict__ v, const int* __restrict__ vids,
             const float* __restrict__ mask,
             const float* __restrict__ u_same, const float* __restrict__ u_cross,
             float* __restrict__ o) {
    extern __shared__ uint32_t sm[];
    uint32_t* Qs = sm;
    uint32_t* Ks = sm + 4352;
    uint32_t* Vs = sm + 8704;
    uint32_t* Ps = sm + 13312;
    int*   svid  = (int*)(sm + 17664);
    float* smask = (float*)(sm + 17728);

    const int tid  = threadIdx.x;
    const int warp = tid >> 5;
    const int lane = tid & 31;
    const int g    = lane >> 2;
    const int tg   = lane & 3;
    const int qw   = warp * 16;

    int qt = blockIdx.x & (SS / 64 - 1);
    int bh = blockIdx.x / (SS / 64);
    int hh = bh & (HH - 1);
    int b  = bh / HH;
    int q0 = qt * 64;

    const float us = u_same[hh], uc = u_cross[hh];

    {
        const float* qbase = q + ((size_t)(b * SS + q0)) * DD + hh * HD;
#pragma unroll
        for (int r = 0; r < 8; r++) {
            int idx = tid + r * 128;
            int qi  = idx >> 4;
            int c4  = (idx & 15) * 4;
            float4 a = *(const float4*)(qbase + (size_t)qi * DD + c4);
            *(uint4*)&Qs[qi * QST + c4] =
                make_uint4(f2tf(a.x), f2tf(a.y), f2tf(a.z), f2tf(a.w));
        }
    }

    int vq0 = vids[b * SS + q0 + qw + g];
    int vq1 = vids[b * SS + q0 + qw + g + 8];
    float m0 = -1e30f, m1 = -1e30f, l0 = 0.0f, l1 = 0.0f;
    float oacc[8][4];
#pragma unroll
    for (int nt = 0; nt < 8; nt++)
#pragma unroll
        for (int r = 0; r < 4; r++) oacc[nt][r] = 0.0f;
    __syncthreads();

    for (int kt = 0; kt < SS; kt += 64) {
        const float* kbase = k + ((size_t)(b * SS + kt)) * DD + hh * HD;
        const float* vbase = v + ((size_t)(b * SS + kt)) * DD + hh * HD;
#pragma unroll
        for (int r = 0; r < 8; r++) {
            int idx = tid + r * 128;
            int ki  = idx >> 4;
            int c4  = (idx & 15) * 4;
            float4 a = *(const float4*)(kbase + (size_t)ki * DD + c4);
            *(uint4*)&Ks[ki * QST + c4] =
                make_uint4(f2tf(a.x), f2tf(a.y), f2tf(a.z), f2tf(a.w));
            float4 bb = *(const float4*)(vbase + (size_t)ki * DD + c4);
            *(uint4*)&Vs[ki * VST + c4] =
                make_uint4(f2tf(bb.x), f2tf(bb.y), f2tf(bb.z), f2tf(bb.w));
        }
        if (tid < 64) {
            svid[tid]  = vids[b * SS + kt + tid];
            smask[tid] = (1.0f - mask[b * SS + kt + tid]) * -1e9f;
        }
        __syncthreads();

        float s[8][4];
#pragma unroll
        for (int nt = 0; nt < 8; nt++)
#pragma unroll
            for (int r = 0; r < 4; r++) s[nt][r] = 0.0f;
#pragma unroll
        for (int ks = 0; ks < 64; ks += 8) {
            uint32_t av[4];
            av[0] = Qs[(qw + g)     * QST + ks + tg];
            av[1] = Qs[(qw + g + 8) * QST + ks + tg];
            av[2] = Qs[(qw + g)     * QST + ks + tg + 4];
            av[3] = Qs[(qw + g + 8) * QST + ks + tg + 4];
#pragma unroll
            for (int nt = 0; nt < 8; nt++) {
                uint32_t bv[2];
                bv[0] = Ks[(nt * 8 + g) * QST + ks + tg];
                bv[1] = Ks[(nt * 8 + g) * QST + ks + tg + 4];
                mma_tf32(s[nt], av, bv);
            }
        }

        float rmax0 = -1e30f, rmax1 = -1e30f;
#pragma unroll
        for (int nt = 0; nt < 8; nt++) {
            int c0 = nt * 8 + 2 * tg;
            int c1 = c0 + 1;
            float bia0 = smask[c0], bia1 = smask[c1];
            s[nt][0] = s[nt][0] * 0.125f + (svid[c0] == vq0 ? us : uc) + bia0;
            s[nt][1] = s[nt][1] * 0.125f + (svid[c1] == vq0 ? us : uc) + bia1;
            s[nt][2] = s[nt][2] * 0.125f + (svid[c0] == vq1 ? us : uc) + bia0;
            s[nt][3] = s[nt][3] * 0.125f + (svid[c1] == vq1 ? us : uc) + bia1;
            rmax0 = fmaxf(rmax0, fmaxf(s[nt][0], s[nt][1]));
            rmax1 = fmaxf(rmax1, fmaxf(s[nt][2], s[nt][3]));
        }
        rmax0 = fmaxf(rmax0, __shfl_xor_sync(0xFFFFFFFF, rmax0, 1));
        rmax0 = fmaxf(rmax0, __shfl_xor_sync(0xFFFFFFFF, rmax0, 2));
        rmax1 = fmaxf(rmax1, __shfl_xor_sync(0xFFFFFFFF, rmax1, 1));
        rmax1 = fmaxf(rmax1, __shfl_xor_sync(0xFFFFFFFF, rmax1, 2));
        float newm0 = fmaxf(m0, rmax0);
        float newm1 = fmaxf(m1, rmax1);
        float corr0 = __expf(m0 - newm0);
        float corr1 = __expf(m1 - newm1);
        m0 = newm0; m1 = newm1;

        float rsum0 = 0.0f, rsum1 = 0.0f;
#pragma unroll
        for (int nt = 0; nt < 8; nt++) {
            float p0 = __expf(s[nt][0] - m0);
            float p1 = __expf(s[nt][1] - m0);
            float p2 = __expf(s[nt][2] - m1);
            float p3 = __expf(s[nt][3] - m1);
            rsum0 += p0 + p1;
            rsum1 += p2 + p3;
            int c0 = nt * 8 + 2 * tg;
            Ps[(qw + g)     * QST + c0]     = f2tf(p0);
            Ps[(qw + g)     * QST + c0 + 1] = f2tf(p1);
            Ps[(qw + g + 8) * QST + c0]     = f2tf(p2);
            Ps[(qw + g + 8) * QST + c0 + 1] = f2tf(p3);
            oacc[nt][0] *= corr0;
            oacc[nt][1] *= corr0;
            oacc[nt][2] *= corr1;
            oacc[nt][3] *= corr1;
        }
        rsum0 += __shfl_xor_sync(0xFFFFFFFF, rsum0, 1);
        rsum0 += __shfl_xor_sync(0xFFFFFFFF, rsum0, 2);
        rsum1 += __shfl_xor_sync(0xFFFFFFFF, rsum1, 1);
        rsum1 += __shfl_xor_sync(0xFFFFFFFF, rsum1, 2);
        l0 = l0 * corr0 + rsum0;
        l1 = l1 * corr1 + rsum1;
        __syncwarp();

#pragma unroll
        for (int ks = 0; ks < 64; ks += 8) {
            uint32_t av[4];
            av[0] = Ps[(qw + g)     * QST + ks + tg];
            av[1] = Ps[(qw + g + 8) * QST + ks + tg];
            av[2] = Ps[(qw + g)     * QST + ks + tg + 4];
            av[3] = Ps[(qw + g + 8) * QST + ks + tg + 4];
#pragma unroll
            for (int nt = 0; nt < 8; nt++) {
                uint32_t bv[2];
                bv[0] = Vs[(ks + tg)     * VST + nt * 8 + g];
                bv[1] = Vs[(ks + tg + 4) * VST + nt * 8 + g];
                mma_tf32(oacc[nt], av, bv);
            }
        }
        __syncthreads();
    }

    float invl0 = 1.0f / l0;
    float invl1 = 1.0f / l1;
    float* ob0 = o + ((size_t)(b * SS + q0 + qw + g)) * DD + hh * HD;
    float* ob1 = ob0 + (size_t)8 * DD;
#pragma unroll
    for (int nt = 0; nt < 8; nt++) {
        int c = nt * 8 + 2 * tg;
        *(float2*)(ob0 + c) = make_float2(oacc[nt][0] * invl0, oacc[nt][1] * invl0);
        *(float2*)(ob1 + c) = make_float2(oacc[nt][2] * invl1, oacc[nt][3] * invl1);
    }
}

// ---------------- driver -----------------------------------------------------
extern "C" void kernel_launch(void* const* d_in, const int* in_sizes, int n_in,
                              void* d_out, int out_size) {
    const float* x      = (const float*)d_in[0];
    const int*   vids   = (const int*)  d_in[1];
    const float* mask   = (const float*)d_in[2];
    const float* W_pe   = (const float*)d_in[3];
    const float* b_pe   = (const float*)d_in[4];
    const float* Wq     = (const float*)d_in[5];
    const float* bq     = (const float*)d_in[6];
    const float* Wk     = (const float*)d_in[7];
    const float* bk     = (const float*)d_in[8];
    const float* Wv     = (const float*)d_in[9];
    const float* bv     = (const float*)d_in[10];
    const float* Wo     = (const float*)d_in[11];
    const float* bo     = (const float*)d_in[12];
    const float* u_same = (const float*)d_in[13];
    const float* u_cross= (const float*)d_in[14];
    const float* g1     = (const float*)d_in[15];
    const float* be1    = (const float*)d_in[16];
    const float* W1     = (const float*)d_in[17];
    const float* b1f    = (const float*)d_in[18];
    const float* W2     = (const float*)d_in[19];
    const float* b2f    = (const float*)d_in[20];
    const float* g2     = (const float*)d_in[21];
    const float* be2    = (const float*)d_in[22];
    const float* Wh     = (const float*)d_in[23];
    const float* bh     = (const float*)d_in[24];
    float* out = (float*)d_out;

    float *ph, *pq, *pk, *pv, *po, *pt, *pff, *pc, *ps;
    cudaGetSymbolAddress((void**)&ph,  g_h);
    cudaGetSymbolAddress((void**)&pq,  g_q);
    cudaGetSymbolAddress((void**)&pk,  g_k);
    cudaGetSymbolAddress((void**)&pv,  g_v);
    cudaGetSymbolAddress((void**)&po,  g_o);
    cudaGetSymbolAddress((void**)&pt,  g_t);
    cudaGetSymbolAddress((void**)&pff, g_ff);
    cudaGetSymbolAddress((void**)&pc,  g_cos);
    cudaGetSymbolAddress((void**)&ps,  g_sin);

    static int smem_set = 0;
    if (!smem_set) {
        cudaFuncSetAttribute(attn3_kernel, cudaFuncAttributeMaxDynamicSharedMemorySize,
                             ATTN_SMEM_U32 * 4);
        smem_set = 1;
    }

    rope_tables_kernel<<<(SS * 32 + 255) / 256, 256>>>(pc, ps);
    tgemm_bias<0><<<dim3(DD / 128, MM / 128), 128>>>(
        x, W_pe, W_pe, W_pe, b_pe, b_pe, b_pe, ph, ph, ph, MM, DD, PP, DD / 128);

    for (int l = 0; l < LL; l++) {
        const float* Wql = Wq + (size_t)l * DD * DD;
        const float* Wkl = Wk + (size_t)l * DD * DD;
        const float* Wvl = Wv + (size_t)l * DD * DD;
        const float* Wol = Wo + (size_t)l * DD * DD;
        const float* W1l = W1 + (size_t)l * DD * DF;
        const float* W2l = W2 + (size_t)l * DF * DD;

        // fused Q,K,V projection
        tgemm_bias<0><<<dim3(3 * (DD / 128), MM / 128), 128>>>(
            ph, Wql, Wkl, Wvl, bq + l * DD, bk + l * DD, bv + l * DD,
            pq, pk, pv, MM, DD, DD, DD / 128);

        rope_apply_kernel<<<(2 * MM * HH * 32) / 256, 256>>>(pq, pk, pc, ps);

        attn3_kernel<<<BB * HH * (SS / 64), 128, ATTN_SMEM_U32 * 4>>>(
            pq, pk, pv, vids, mask, u_same + l * HH, u_cross + l * HH, po);

        tgemm_bias<0><<<dim3(DD / 128, MM / 128), 128>>>(
            po, Wol, Wol, Wol, bo + l * DD, bo + l * DD, bo + l * DD,
            pt, pt, pt, MM, DD, DD, DD / 128);
        add_ln_kernel<<<MM, 128>>>(ph, pt, g1 + l * DD, be1 + l * DD);

        tgemm_bias<1><<<dim3(DF / 128, MM / 128), 128>>>(
            ph, W1l, W1l, W1l, b1f + l * DF, b1f + l * DF, b1f + l * DF,
            pff, pff, pff, MM, DF, DD, DF / 128);
        tgemm_bias<0><<<dim3(DD / 128, MM / 128), 128>>>(
            pff, W2l, W2l, W2l, b2f + l * DD, b2f + l * DD, b2f + l * DD,
            pt, pt, pt, MM, DD, DF, DD / 128);
        add_ln_kernel<<<MM, 128>>>(ph, pt, g2 + l * DD, be2 + l * DD);
    }

    head_gemm_kernel<<<(MM * PP) / 256, 256>>>(ph, Wh, bh, out);
}

// round 7
// speedup vs baseline: 1.2254x; 1.2254x over previous
#include <cuda_runtime.h>
#include <cuda_fp16.h>
#include <math.h>
#include <stdint.h>

#define BB  4
#define SS  2048
#define PP  32
#define DD  512
#define HH  8
#define LL  2
#define DF  2048
#define HD  64
#define MM  (BB*SS)   /* 8192 rows */

// ---------------- scratch (device globals; no allocations allowed) ----------
__device__ float g_h [MM*DD];
__device__ float g_q [MM*DD];
__device__ float g_k [MM*DD];
__device__ float g_v [MM*DD];
__device__ float g_o [MM*DD];
__device__ float g_t [MM*DD];
__device__ float g_ff[MM*DF];
__device__ float g_cos[SS*32];
__device__ float g_sin[SS*32];

// ---------------- RoPE tables ----------------------------------------------
__global__ void rope_tables_kernel(float* __restrict__ ct, float* __restrict__ st) {
    int idx = blockIdx.x * blockDim.x + threadIdx.x;
    if (idx >= SS * 32) return;
    int pos = idx >> 5;
    int i   = idx & 31;
    int fidx = (2 * i) & 31;
    float ex  = (float)(2 * fidx) / 64.0f;
    float inv = 1.0f / powf(10000.0f, ex);
    float ang = (float)pos * inv;
    ct[idx] = cosf(ang);
    st[idx] = sinf(ang);
}

// one launch applies RoPE to both q and k
__global__ void rope_apply_kernel(float* __restrict__ q, float* __restrict__ k,
                                  const float* __restrict__ ct,
                                  const float* __restrict__ st) {
    int gidx = blockIdx.x * blockDim.x + threadIdx.x;   // 2*MM*HH*32 threads
    float* base = (gidx < MM * HH * 32) ? q : k;
    int idx = (gidx < MM * HH * 32) ? gidx : gidx - MM * HH * 32;
    int i   = idx & 31;
    int rem = idx >> 5;
    int hh  = rem & (HH - 1);
    int row = rem >> 3;
    int s   = row & (SS - 1);
    float c  = ct[s * 32 + i];
    float sn = st[s * 32 + i];
    float* p = base + (size_t)row * DD + hh * HD + 2 * i;
    float x1 = p[0], x2 = p[1];
    p[0] = x1 * c - x2 * sn;
    p[1] = x1 * sn + x2 * c;
}

// ---------------- tf32 helpers (attention) ----------------------------------
__device__ __forceinline__ uint32_t f2tf(float f) {
    uint32_t u;
    asm("cvt.rna.tf32.f32 %0, %1;" : "=r"(u) : "f"(f));
    return u;
}

__device__ __forceinline__ void mma_tf32(float* c, const uint32_t* a, const uint32_t* b) {
    asm volatile(
        "mma.sync.aligned.m16n8k8.row.col.f32.tf32.tf32.f32 "
        "{%0,%1,%2,%3}, {%4,%5,%6,%7}, {%8,%9}, {%0,%1,%2,%3};\n"
        : "+f"(c[0]), "+f"(c[1]), "+f"(c[2]), "+f"(c[3])
        : "r"(a[0]), "r"(a[1]), "r"(a[2]), "r"(a[3]), "r"(b[0]), "r"(b[1]));
}

// ---------------- fp16 helpers (GEMM) ----------------------------------------
__device__ __forceinline__ void mma_f16(float* c, const uint32_t* a, const uint32_t* b) {
    asm volatile(
        "mma.sync.aligned.m16n8k16.row.col.f32.f16.f16.f32 "
        "{%0,%1,%2,%3}, {%4,%5,%6,%7}, {%8,%9}, {%0,%1,%2,%3};\n"
        : "+f"(c[0]), "+f"(c[1]), "+f"(c[2]), "+f"(c[3])
        : "r"(a[0]), "r"(a[1]), "r"(a[2]), "r"(a[3]), "r"(b[0]), "r"(b[1]));
}

__device__ __forceinline__ uint32_t pack_h2(float lo, float hi) {
    __half2 h = __floats2half2_rn(lo, hi);
    return *(uint32_t*)&h;
}

// ---------------- FP16 tensor-core GEMM --------------------------------------
// C = A[MxK] @ Bsel[KxN] + bias_sel, optional GELU.
// Block 128x128x16, 8 warps (2M x 4N), warp tile 64x32, mma.m16n8k16.f16,
// double-buffered smem. As [m][k] halfs stride 24; Bs TRANSPOSED [n][k] halfs
// stride 24 (fragment banks 12g+tg: bijective mod 32, conflict-free).
#define AST 24
#define KST 24

template <int GELU>
__global__ void __launch_bounds__(256)
tgemm_bias(const float* __restrict__ A,
           const float* __restrict__ B0, const float* __restrict__ B1,
           const float* __restrict__ B2,
           const float* __restrict__ bias0, const float* __restrict__ bias1,
           const float* __restrict__ bias2,
           float* __restrict__ C0, float* __restrict__ C1, float* __restrict__ C2,
           int M, int N, int K, int ntile) {
    __shared__ __half As[2][128 * AST];
    __shared__ __half Bs[2][128 * KST];

    const int sel = blockIdx.x / ntile;
    const int bx  = blockIdx.x - sel * ntile;
    const int by  = blockIdx.y;
    const float* B    = (sel == 0) ? B0 : (sel == 1) ? B1 : B2;
    const float* bias = (sel == 0) ? bias0 : (sel == 1) ? bias1 : bias2;
    float*       C    = (sel == 0) ? C0 : (sel == 1) ? C1 : C2;

    const int tid  = threadIdx.x;
    const int warp = tid >> 5;
    const int lane = tid & 31;
    const int g    = lane >> 2;
    const int tg   = lane & 3;
    const int wm   = (warp & 1) * 64;
    const int wn   = (warp >> 1) * 32;

    // A staging: thread -> (row = tid>>1, k0 = (tid&1)*8), 8 halfs
    const int aRow = tid >> 1;
    const int aK0  = (tid & 1) * 8;
    // B staging: thread -> (n = tid&127, kh = (tid>>7)*8), 8 halfs [n][k]
    const int bN  = tid & 127;
    const int bKh = (tid >> 7) * 8;

    const float* Ap = A + (size_t)(by * 128 + aRow) * K + aK0;
    const float* Bp = B + (size_t)bKh * N + bx * 128 + bN;

    float acc[4][4][4];
#pragma unroll
    for (int i = 0; i < 4; i++)
#pragma unroll
        for (int j = 0; j < 4; j++)
#pragma unroll
            for (int r = 0; r < 4; r++) acc[i][j][r] = 0.0f;

    float4 a0, a1;
    float  bR[8];

    // prefetch stage 0
    a0 = *(const float4*)(Ap);
    a1 = *(const float4*)(Ap + 4);
#pragma unroll
    for (int j = 0; j < 8; j++) bR[j] = Bp[(size_t)j * N];
    Ap += 16;
    Bp += (size_t)16 * N;

    // store stage 0
    {
        uint4 av = make_uint4(pack_h2(a0.x, a0.y), pack_h2(a0.z, a0.w),
                              pack_h2(a1.x, a1.y), pack_h2(a1.z, a1.w));
        *(uint4*)&As[0][aRow * AST + aK0] = av;
        uint4 bv = make_uint4(pack_h2(bR[0], bR[1]), pack_h2(bR[2], bR[3]),
                              pack_h2(bR[4], bR[5]), pack_h2(bR[6], bR[7]));
        *(uint4*)&Bs[0][bN * KST + bKh] = bv;
    }
    __syncthreads();

    const int nIter = K >> 4;
    for (int it = 0; it < nIter; it++) {
        const int buf = it & 1;
        const bool more = (it + 1 < nIter);

        if (more) {
            a0 = *(const float4*)(Ap);
            a1 = *(const float4*)(Ap + 4);
#pragma unroll
            for (int j = 0; j < 8; j++) bR[j] = Bp[(size_t)j * N];
            Ap += 16;
            Bp += (size_t)16 * N;
        }

        // one k16 step
        {
            uint32_t af[4][4], bf[4][2];
#pragma unroll
            for (int mt = 0; mt < 4; mt++) {
                int m = wm + mt * 16;
                af[mt][0] = *(const uint32_t*)&As[buf][(m + g)     * AST + 2 * tg];
                af[mt][1] = *(const uint32_t*)&As[buf][(m + g + 8) * AST + 2 * tg];
                af[mt][2] = *(const uint32_t*)&As[buf][(m + g)     * AST + 2 * tg + 8];
                af[mt][3] = *(const uint32_t*)&As[buf][(m + g + 8) * AST + 2 * tg + 8];
            }
#pragma unroll
            for (int nt = 0; nt < 4; nt++) {
                int n = wn + nt * 8 + g;
                bf[nt][0] = *(const uint32_t*)&Bs[buf][n * KST + 2 * tg];
                bf[nt][1] = *(const uint32_t*)&Bs[buf][n * KST + 2 * tg + 8];
            }
#pragma unroll
            for (int mt = 0; mt < 4; mt++)
#pragma unroll
                for (int nt = 0; nt < 4; nt++)
                    mma_f16(acc[mt][nt], af[mt], bf[nt]);
        }

        if (more) {
            int nb = buf ^ 1;
            uint4 av = make_uint4(pack_h2(a0.x, a0.y), pack_h2(a0.z, a0.w),
                                  pack_h2(a1.x, a1.y), pack_h2(a1.z, a1.w));
            *(uint4*)&As[nb][aRow * AST + aK0] = av;
            uint4 bv = make_uint4(pack_h2(bR[0], bR[1]), pack_h2(bR[2], bR[3]),
                                  pack_h2(bR[4], bR[5]), pack_h2(bR[6], bR[7]));
            *(uint4*)&Bs[nb][bN * KST + bKh] = bv;
            __syncthreads();
        }
    }

    // epilogue: bias (+GELU)
#pragma unroll
    for (int mt = 0; mt < 4; mt++) {
#pragma unroll
        for (int nt = 0; nt < 4; nt++) {
            int row0 = by * 128 + wm + mt * 16 + g;
            int col  = bx * 128 + wn + nt * 8 + 2 * tg;
            float bc0 = bias[col], bc1 = bias[col + 1];
            float v0 = acc[mt][nt][0] + bc0;
            float v1 = acc[mt][nt][1] + bc1;
            float v2 = acc[mt][nt][2] + bc0;
            float v3 = acc[mt][nt][3] + bc1;
            if (GELU) {
                v0 = 0.5f * v0 * (1.0f + erff(v0 * 0.70710678118654752f));
                v1 = 0.5f * v1 * (1.0f + erff(v1 * 0.70710678118654752f));
                v2 = 0.5f * v2 * (1.0f + erff(v2 * 0.70710678118654752f));
                v3 = 0.5f * v3 * (1.0f + erff(v3 * 0.70710678118654752f));
            }
            *(float2*)(C + (size_t)row0 * N + col)       = make_float2(v0, v1);
            *(float2*)(C + (size_t)(row0 + 8) * N + col) = make_float2(v2, v3);
        }
    }
}

// ---------------- naive head GEMM: out[M x 32] = h @ Wh + bh ----------------
__global__ void head_gemm_kernel(const float* __restrict__ h,
                                 const float* __restrict__ Wh,
                                 const float* __restrict__ bh,
                                 float* __restrict__ out) {
    int idx = blockIdx.x * blockDim.x + threadIdx.x;
    int n = idx & (PP - 1);
    int m = idx / PP;
    float acc = bh[n];
    const float* hp = h + (size_t)m * DD;
#pragma unroll 8
    for (int k = 0; k < DD; k++) acc += hp[k] * Wh[k * PP + n];
    out[idx] = acc;
}

// ---------------- residual add + LayerNorm (in-place into h) ----------------
__global__ void add_ln_kernel(float* __restrict__ h, const float* __restrict__ d,
                              const float* __restrict__ g, const float* __restrict__ b) {
    int row = blockIdx.x;
    int t   = threadIdx.x;
    float4 hv = *(float4*)(h + (size_t)row * DD + t * 4);
    float4 dv = *(const float4*)(d + (size_t)row * DD + t * 4);
    float v0 = hv.x + dv.x, v1 = hv.y + dv.y, v2 = hv.z + dv.z, v3 = hv.w + dv.w;
    float s  = v0 + v1 + v2 + v3;
    float s2 = v0 * v0 + v1 * v1 + v2 * v2 + v3 * v3;
#pragma unroll
    for (int off = 16; off; off >>= 1) {
        s  += __shfl_xor_sync(0xFFFFFFFF, s,  off);
        s2 += __shfl_xor_sync(0xFFFFFFFF, s2, off);
    }
    __shared__ float sh[8];
    int w = t >> 5, lane = t & 31;
    if (lane == 0) { sh[w] = s; sh[4 + w] = s2; }
    __syncthreads();
    s  = sh[0] + sh[1] + sh[2] + sh[3];
    s2 = sh[4] + sh[5] + sh[6] + sh[7];
    float mean = s * (1.0f / DD);
    float var  = s2 * (1.0f / DD) - mean * mean;
    float inv  = rsqrtf(var + 1e-5f);
    float4 gv = *(const float4*)(g + t * 4);
    float4 bv = *(const float4*)(b + t * 4);
    float4 o;
    o.x = (v0 - mean) * inv * gv.x + bv.x;
    o.y = (v1 - mean) * inv * gv.y + bv.y;
    o.z = (v2 - mean) * inv * gv.z + bv.z;
    o.w = (v3 - mean) * inv * gv.w + bv.w;
    *(float4*)(h + (size_t)row * DD + t * 4) = o;
}

// ---------------- tf32 tensor-core flash attention ---------------------------
#define ATTN_SMEM_U32 17792
#define QST 68
#define VST 72

__global__ void __launch_bounds__(128)
attn3_kernel(const float* __restrict__ q, const float* __restrict__ k,
             const float* __restrict__ v, const int* __restrict__ vids,
             const float* __restrict__ mask,
             const float* __restrict__ u_same, const float* __restrict__ u_cross,
             float* __restrict__ o) {
    extern __shared__ uint32_t sm[];
    uint32_t* Qs = sm;
    uint32_t* Ks = sm + 4352;
    uint32_t* Vs = sm + 8704;
    uint32_t* Ps = sm + 13312;
    int*   svid  = (int*)(sm + 17664);
    float* smask = (float*)(sm + 17728);

    const int tid  = threadIdx.x;
    const int warp = tid >> 5;
    const int lane = tid & 31;
    const int g    = lane >> 2;
    const int tg   = lane & 3;
    const int qw   = warp * 16;

    int qt = blockIdx.x & (SS / 64 - 1);
    int bh = blockIdx.x / (SS / 64);
    int hh = bh & (HH - 1);
    int b  = bh / HH;
    int q0 = qt * 64;

    const float us = u_same[hh], uc = u_cross[hh];

    {
        const float* qbase = q + ((size_t)(b * SS + q0)) * DD + hh * HD;
#pragma unroll
        for (int r = 0; r < 8; r++) {
            int idx = tid + r * 128;
            int qi  = idx >> 4;
            int c4  = (idx & 15) * 4;
            float4 a = *(const float4*)(qbase + (size_t)qi * DD + c4);
            *(uint4*)&Qs[qi * QST + c4] =
                make_uint4(f2tf(a.x), f2tf(a.y), f2tf(a.z), f2tf(a.w));
        }
    }

    int vq0 = vids[b * SS + q0 + qw + g];
    int vq1 = vids[b * SS + q0 + qw + g + 8];
    float m0 = -1e30f, m1 = -1e30f, l0 = 0.0f, l1 = 0.0f;
    float oacc[8][4];
#pragma unroll
    for (int nt = 0; nt < 8; nt++)
#pragma unroll
        for (int r = 0; r < 4; r++) oacc[nt][r] = 0.0f;
    __syncthreads();

    for (int kt = 0; kt < SS; kt += 64) {
        const float* kbase = k + ((size_t)(b * SS + kt)) * DD + hh * HD;
        const float* vbase = v + ((size_t)(b * SS + kt)) * DD + hh * HD;
#pragma unroll
        for (int r = 0; r < 8; r++) {
            int idx = tid + r * 128;
            int ki  = idx >> 4;
            int c4  = (idx & 15) * 4;
            float4 a = *(const float4*)(kbase + (size_t)ki * DD + c4);
            *(uint4*)&Ks[ki * QST + c4] =
                make_uint4(f2tf(a.x), f2tf(a.y), f2tf(a.z), f2tf(a.w));
            float4 bb = *(const float4*)(vbase + (size_t)ki * DD + c4);
            *(uint4*)&Vs[ki * VST + c4] =
                make_uint4(f2tf(bb.x), f2tf(bb.y), f2tf(bb.z), f2tf(bb.w));
        }
        if (tid < 64) {
            svid[tid]  = vids[b * SS + kt + tid];
            smask[tid] = (1.0f - mask[b * SS + kt + tid]) * -1e9f;
        }
        __syncthreads();

        float s[8][4];
#pragma unroll
        for (int nt = 0; nt < 8; nt++)
#pragma unroll
            for (int r = 0; r < 4; r++) s[nt][r] = 0.0f;
#pragma unroll
        for (int ks = 0; ks < 64; ks += 8) {
            uint32_t av[4];
            av[0] = Qs[(qw + g)     * QST + ks + tg];
            av[1] = Qs[(qw + g + 8) * QST + ks + tg];
            av[2] = Qs[(qw + g)     * QST + ks + tg + 4];
            av[3] = Qs[(qw + g + 8) * QST + ks + tg + 4];
#pragma unroll
            for (int nt = 0; nt < 8; nt++) {
                uint32_t bv[2];
                bv[0] = Ks[(nt * 8 + g) * QST + ks + tg];
                bv[1] = Ks[(nt * 8 + g) * QST + ks + tg + 4];
                mma_tf32(s[nt], av, bv);
            }
        }

        float rmax0 = -1e30f, rmax1 = -1e30f;
#pragma unroll
        for (int nt = 0; nt < 8; nt++) {
            int c0 = nt * 8 + 2 * tg;
            int c1 = c0 + 1;
            float bia0 = smask[c0], bia1 = smask[c1];
            s[nt][0] = s[nt][0] * 0.125f + (svid[c0] == vq0 ? us : uc) + bia0;
            s[nt][1] = s[nt][1] * 0.125f + (svid[c1] == vq0 ? us : uc) + bia1;
            s[nt][2] = s[nt][2] * 0.125f + (svid[c0] == vq1 ? us : uc) + bia0;
            s[nt][3] = s[nt][3] * 0.125f + (svid[c1] == vq1 ? us : uc) + bia1;
            rmax0 = fmaxf(rmax0, fmaxf(s[nt][0], s[nt][1]));
            rmax1 = fmaxf(rmax1, fmaxf(s[nt][2], s[nt][3]));
        }
        rmax0 = fmaxf(rmax0, __shfl_xor_sync(0xFFFFFFFF, rmax0, 1));
        rmax0 = fmaxf(rmax0, __shfl_xor_sync(0xFFFFFFFF, rmax0, 2));
        rmax1 = fmaxf(rmax1, __shfl_xor_sync(0xFFFFFFFF, rmax1, 1));
        rmax1 = fmaxf(rmax1, __shfl_xor_sync(0xFFFFFFFF, rmax1, 2));
        float newm0 = fmaxf(m0, rmax0);
        float newm1 = fmaxf(m1, rmax1);
        float corr0 = __expf(m0 - newm0);
        float corr1 = __expf(m1 - newm1);
        m0 = newm0; m1 = newm1;

        float rsum0 = 0.0f, rsum1 = 0.0f;
#pragma unroll
        for (int nt = 0; nt < 8; nt++) {
            float p0 = __expf(s[nt][0] - m0);
            float p1 = __expf(s[nt][1] - m0);
            float p2 = __expf(s[nt][2] - m1);
            float p3 = __expf(s[nt][3] - m1);
            rsum0 += p0 + p1;
            rsum1 += p2 + p3;
            int c0 = nt * 8 + 2 * tg;
            Ps[(qw + g)     * QST + c0]     = f2tf(p0);
            Ps[(qw + g)     * QST + c0 + 1] = f2tf(p1);
            Ps[(qw + g + 8) * QST + c0]     = f2tf(p2);
            Ps[(qw + g + 8) * QST + c0 + 1] = f2tf(p3);
            oacc[nt][0] *= corr0;
            oacc[nt][1] *= corr0;
            oacc[nt][2] *= corr1;
            oacc[nt][3] *= corr1;
        }
        rsum0 += __shfl_xor_sync(0xFFFFFFFF, rsum0, 1);
        rsum0 += __shfl_xor_sync(0xFFFFFFFF, rsum0, 2);
        rsum1 += __shfl_xor_sync(0xFFFFFFFF, rsum1, 1);
        rsum1 += __shfl_xor_sync(0xFFFFFFFF, rsum1, 2);
        l0 = l0 * corr0 + rsum0;
        l1 = l1 * corr1 + rsum1;
        __syncwarp();

#pragma unroll
        for (int ks = 0; ks < 64; ks += 8) {
            uint32_t av[4];
            av[0] = Ps[(qw + g)     * QST + ks + tg];
            av[1] = Ps[(qw + g + 8) * QST + ks + tg];
            av[2] = Ps[(qw + g)     * QST + ks + tg + 4];
            av[3] = Ps[(qw + g + 8) * QST + ks + tg + 4];
#pragma unroll
            for (int nt = 0; nt < 8; nt++) {
                uint32_t bv[2];
                bv[0] = Vs[(ks + tg)     * VST + nt * 8 + g];
                bv[1] = Vs[(ks + tg + 4) * VST + nt * 8 + g];
                mma_tf32(oacc[nt], av, bv);
            }
        }
        __syncthreads();
    }

    float invl0 = 1.0f / l0;
    float invl1 = 1.0f / l1;
    float* ob0 = o + ((size_t)(b * SS + q0 + qw + g)) * DD + hh * HD;
    float* ob1 = ob0 + (size_t)8 * DD;
#pragma unroll
    for (int nt = 0; nt < 8; nt++) {
        int c = nt * 8 + 2 * tg;
        *(float2*)(ob0 + c) = make_float2(oacc[nt][0] * invl0, oacc[nt][1] * invl0);
        *(float2*)(ob1 + c) = make_float2(oacc[nt][2] * invl1, oacc[nt][3] * invl1);
    }
}

// ---------------- driver -----------------------------------------------------
extern "C" void kernel_launch(void* const* d_in, const int* in_sizes, int n_in,
                              void* d_out, int out_size) {
    const float* x      = (const float*)d_in[0];
    const int*   vids   = (const int*)  d_in[1];
    const float* mask   = (const float*)d_in[2];
    const float* W_pe   = (const float*)d_in[3];
    const float* b_pe   = (const float*)d_in[4];
    const float* Wq     = (const float*)d_in[5];
    const float* bq     = (const float*)d_in[6];
    const float* Wk     = (const float*)d_in[7];
    const float* bk     = (const float*)d_in[8];
    const float* Wv     = (const float*)d_in[9];
    const float* bv     = (const float*)d_in[10];
    const float* Wo     = (const float*)d_in[11];
    const float* bo     = (const float*)d_in[12];
    const float* u_same = (const float*)d_in[13];
    const float* u_cross= (const float*)d_in[14];
    const float* g1     = (const float*)d_in[15];
    const float* be1    = (const float*)d_in[16];
    const float* W1     = (const float*)d_in[17];
    const float* b1f    = (const float*)d_in[18];
    const float* W2     = (const float*)d_in[19];
    const float* b2f    = (const float*)d_in[20];
    const float* g2     = (const float*)d_in[21];
    const float* be2    = (const float*)d_in[22];
    const float* Wh     = (const float*)d_in[23];
    const float* bh     = (const float*)d_in[24];
    float* out = (float*)d_out;

    float *ph, *pq, *pk, *pv, *po, *pt, *pff, *pc, *ps;
    cudaGetSymbolAddress((void**)&ph,  g_h);
    cudaGetSymbolAddress((void**)&pq,  g_q);
    cudaGetSymbolAddress((void**)&pk,  g_k);
    cudaGetSymbolAddress((void**)&pv,  g_v);
    cudaGetSymbolAddress((void**)&po,  g_o);
    cudaGetSymbolAddress((void**)&pt,  g_t);
    cudaGetSymbolAddress((void**)&pff, g_ff);
    cudaGetSymbolAddress((void**)&pc,  g_cos);
    cudaGetSymbolAddress((void**)&ps,  g_sin);

    static int smem_set = 0;
    if (!smem_set) {
        cudaFuncSetAttribute(attn3_kernel, cudaFuncAttributeMaxDynamicSharedMemorySize,
                             ATTN_SMEM_U32 * 4);
        smem_set = 1;
    }

    rope_tables_kernel<<<(SS * 32 + 255) / 256, 256>>>(pc, ps);
    tgemm_bias<0><<<dim3(DD / 128, MM / 128), 256>>>(
        x, W_pe, W_pe, W_pe, b_pe, b_pe, b_pe, ph, ph, ph, MM, DD, PP, DD / 128);

    for (int l = 0; l < LL; l++) {
        const float* Wql = Wq + (size_t)l * DD * DD;
        const float* Wkl = Wk + (size_t)l * DD * DD;
        const float* Wvl = Wv + (size_t)l * DD * DD;
        const float* Wol = Wo + (size_t)l * DD * DD;
        const float* W1l = W1 + (size_t)l * DD * DF;
        const float* W2l = W2 + (size_t)l * DF * DD;

        // fused Q,K,V projection
        tgemm_bias<0><<<dim3(3 * (DD / 128), MM / 128), 256>>>(
            ph, Wql, Wkl, Wvl, bq + l * DD, bk + l * DD, bv + l * DD,
            pq, pk, pv, MM, DD, DD, DD / 128);

        rope_apply_kernel<<<(2 * MM * HH * 32) / 256, 256>>>(pq, pk, pc, ps);

        attn3_kernel<<<BB * HH * (SS / 64), 128, ATTN_SMEM_U32 * 4>>>(
            pq, pk, pv, vids, mask, u_same + l * HH, u_cross + l * HH, po);

        tgemm_bias<0><<<dim3(DD / 128, MM / 128), 256>>>(
            po, Wol, Wol, Wol, bo + l * DD, bo + l * DD, bo + l * DD,
            pt, pt, pt, MM, DD, DD, DD / 128);
        add_ln_kernel<<<MM, 128>>>(ph, pt, g1 + l * DD, be1 + l * DD);

        tgemm_bias<1><<<dim3(DF / 128, MM / 128), 256>>>(
            ph, W1l, W1l, W1l, b1f + l * DF, b1f + l * DF, b1f + l * DF,
            pff, pff, pff, MM, DF, DD, DF / 128);
        tgemm_bias<0><<<dim3(DD / 128, MM / 128), 256>>>(
            pff, W2l, W2l, W2l, b2f + l * DD, b2f + l * DD, b2f + l * DD,
            pt, pt, pt, MM, DD, DF, DD / 128);
        add_ln_kernel<<<MM, 128>>>(ph, pt, g2 + l * DD, be2 + l * DD);
    }

    head_gemm_kernel<<<(MM * PP) / 256, 256>>>(ph, Wh, bh, out);
}

// round 8
// speedup vs baseline: 1.5555x; 1.2694x over previous
#include <cuda_runtime.h>
#include <cuda_fp16.h>
#include <math.h>
#include <stdint.h>

#define BB  4
#define SS  2048
#define PP  32
#define DD  512
#define HH  8
#define LL  2
#define DF  2048
#define HD  64
#define MM  (BB*SS)   /* 8192 rows */

// ---------------- scratch (device globals; no allocations allowed) ----------
__device__ float  g_h [MM*DD];
__device__ float  g_t [MM*DD];
__device__ __half g_qh [MM*DD];
__device__ __half g_kh [MM*DD];
__device__ __half g_vh [MM*DD];
__device__ __half g_oh [MM*DD];
__device__ __half g_ffh[MM*DF];
__device__ float  g_cos[SS*32];
__device__ float  g_sin[SS*32];

// ---------------- fp16 helpers ----------------------------------------------
__device__ __forceinline__ void mma_f16(float* c, const uint32_t* a, const uint32_t* b) {
    asm volatile(
        "mma.sync.aligned.m16n8k16.row.col.f32.f16.f16.f32 "
        "{%0,%1,%2,%3}, {%4,%5,%6,%7}, {%8,%9}, {%0,%1,%2,%3};\n"
        : "+f"(c[0]), "+f"(c[1]), "+f"(c[2]), "+f"(c[3])
        : "r"(a[0]), "r"(a[1]), "r"(a[2]), "r"(a[3]), "r"(b[0]), "r"(b[1]));
}

__device__ __forceinline__ uint32_t pack_h2(float lo, float hi) {
    __half2 h = __floats2half2_rn(lo, hi);
    return *(uint32_t*)&h;
}

__device__ __forceinline__ void ldmatrix_x2_trans(uint32_t& r0, uint32_t& r1, uint32_t saddr) {
    asm volatile("ldmatrix.sync.aligned.m8n8.x2.trans.shared.b16 {%0,%1}, [%2];"
                 : "=r"(r0), "=r"(r1) : "r"(saddr));
}

// ---------------- RoPE tables ----------------------------------------------
__global__ void rope_tables_kernel(float* __restrict__ ct, float* __restrict__ st) {
    int idx = blockIdx.x * blockDim.x + threadIdx.x;
    if (idx >= SS * 32) return;
    int pos = idx >> 5;
    int i   = idx & 31;
    int fidx = (2 * i) & 31;
    float ex  = (float)(2 * fidx) / 64.0f;
    float inv = 1.0f / powf(10000.0f, ex);
    float ang = (float)pos * inv;
    ct[idx] = cosf(ang);
    st[idx] = sinf(ang);
}

// one launch applies RoPE to both q and k (half storage, fp32 math)
__global__ void rope_apply_kernel(__half* __restrict__ q, __half* __restrict__ k,
                                  const float* __restrict__ ct,
                                  const float* __restrict__ st) {
    int gidx = blockIdx.x * blockDim.x + threadIdx.x;   // 2*MM*HH*32 threads
    __half* base = (gidx < MM * HH * 32) ? q : k;
    int idx = (gidx < MM * HH * 32) ? gidx : gidx - MM * HH * 32;
    int i   = idx & 31;
    int rem = idx >> 5;
    int hh  = rem & (HH - 1);
    int row = rem >> 3;
    int s   = row & (SS - 1);
    float c  = ct[s * 32 + i];
    float sn = st[s * 32 + i];
    __half2* p = (__half2*)(base + (size_t)row * DD + hh * HD + 2 * i);
    float2 x = __half22float2(*p);
    *p = __floats2half2_rn(x.x * c - x.y * sn, x.x * sn + x.y * c);
}

// ---------------- FP16 tensor-core GEMM --------------------------------------
// C = A[MxK] @ Bsel[KxN] + bias_sel. A fp32 or fp16 (INH), C fp32 or fp16 (OUTH).
// Block 128x128x16, 8 warps (2M x 4N), warp tile 64x32, mma.m16n8k16.f16,
// double-buffered. As [m][k] stride 24h; Bs transposed [n][k] stride 24h.
#define AST 24
#define KST 24

template <int GELU, int INH, int OUTH>
__global__ void __launch_bounds__(256)
tgemm_bias(const void* __restrict__ A_,
           const float* __restrict__ B0, const float* __restrict__ B1,
           const float* __restrict__ B2,
           const float* __restrict__ bias0, const float* __restrict__ bias1,
           const float* __restrict__ bias2,
           void* __restrict__ C0, void* __restrict__ C1, void* __restrict__ C2,
           int M, int N, int K, int ntile) {
    __shared__ __half As[2][128 * AST];
    __shared__ __half Bs[2][128 * KST];

    const int sel = blockIdx.x / ntile;
    const int bx  = blockIdx.x - sel * ntile;
    const int by  = blockIdx.y;
    const float* B    = (sel == 0) ? B0 : (sel == 1) ? B1 : B2;
    const float* bias = (sel == 0) ? bias0 : (sel == 1) ? bias1 : bias2;
    void*        C    = (sel == 0) ? C0 : (sel == 1) ? C1 : C2;

    const int tid  = threadIdx.x;
    const int warp = tid >> 5;
    const int lane = tid & 31;
    const int g    = lane >> 2;
    const int tg   = lane & 3;
    const int wm   = (warp & 1) * 64;
    const int wn   = (warp >> 1) * 32;

    const int aRow = tid >> 1;
    const int aK0  = (tid & 1) * 8;
    const int bN  = tid & 127;
    const int bKh = (tid >> 7) * 8;

    const float*  Apf = (const float*)A_  + (size_t)(by * 128 + aRow) * K + aK0;
    const __half* Aph = (const __half*)A_ + (size_t)(by * 128 + aRow) * K + aK0;
    const float*  Bp  = B + (size_t)bKh * N + bx * 128 + bN;

    float acc[4][4][4];
#pragma unroll
    for (int i = 0; i < 4; i++)
#pragma unroll
        for (int j = 0; j < 4; j++)
#pragma unroll
            for (int r = 0; r < 4; r++) acc[i][j][r] = 0.0f;

    uint4 apack;
    float bR[8];

    // prefetch stage 0
    if (INH) {
        apack = *(const uint4*)Aph;  Aph += 16;
    } else {
        float4 a0 = *(const float4*)(Apf);
        float4 a1 = *(const float4*)(Apf + 4);
        apack = make_uint4(pack_h2(a0.x, a0.y), pack_h2(a0.z, a0.w),
                           pack_h2(a1.x, a1.y), pack_h2(a1.z, a1.w));
        Apf += 16;
    }
#pragma unroll
    for (int j = 0; j < 8; j++) bR[j] = Bp[(size_t)j * N];
    Bp += (size_t)16 * N;

    // store stage 0
    *(uint4*)&As[0][aRow * AST + aK0] = apack;
    *(uint4*)&Bs[0][bN * KST + bKh] =
        make_uint4(pack_h2(bR[0], bR[1]), pack_h2(bR[2], bR[3]),
                   pack_h2(bR[4], bR[5]), pack_h2(bR[6], bR[7]));
    __syncthreads();

    const int nIter = K >> 4;
    for (int it = 0; it < nIter; it++) {
        const int buf = it & 1;
        const bool more = (it + 1 < nIter);

        if (more) {
            if (INH) {
                apack = *(const uint4*)Aph;  Aph += 16;
            } else {
                float4 a0 = *(const float4*)(Apf);
                float4 a1 = *(const float4*)(Apf + 4);
                apack = make_uint4(pack_h2(a0.x, a0.y), pack_h2(a0.z, a0.w),
                                   pack_h2(a1.x, a1.y), pack_h2(a1.z, a1.w));
                Apf += 16;
            }
#pragma unroll
            for (int j = 0; j < 8; j++) bR[j] = Bp[(size_t)j * N];
            Bp += (size_t)16 * N;
        }

        {
            uint32_t af[4][4], bf[4][2];
#pragma unroll
            for (int mt = 0; mt < 4; mt++) {
                int m = wm + mt * 16;
                af[mt][0] = *(const uint32_t*)&As[buf][(m + g)     * AST + 2 * tg];
                af[mt][1] = *(const uint32_t*)&As[buf][(m + g + 8) * AST + 2 * tg];
                af[mt][2] = *(const uint32_t*)&As[buf][(m + g)     * AST + 2 * tg + 8];
                af[mt][3] = *(const uint32_t*)&As[buf][(m + g + 8) * AST + 2 * tg + 8];
            }
#pragma unroll
            for (int nt = 0; nt < 4; nt++) {
                int n = wn + nt * 8 + g;
                bf[nt][0] = *(const uint32_t*)&Bs[buf][n * KST + 2 * tg];
                bf[nt][1] = *(const uint32_t*)&Bs[buf][n * KST + 2 * tg + 8];
            }
#pragma unroll
            for (int mt = 0; mt < 4; mt++)
#pragma unroll
                for (int nt = 0; nt < 4; nt++)
                    mma_f16(acc[mt][nt], af[mt], bf[nt]);
        }

        if (more) {
            int nb = buf ^ 1;
            *(uint4*)&As[nb][aRow * AST + aK0] = apack;
            *(uint4*)&Bs[nb][bN * KST + bKh] =
                make_uint4(pack_h2(bR[0], bR[1]), pack_h2(bR[2], bR[3]),
                           pack_h2(bR[4], bR[5]), pack_h2(bR[6], bR[7]));
            __syncthreads();
        }
    }

    // epilogue: bias (+GELU)
#pragma unroll
    for (int mt = 0; mt < 4; mt++) {
#pragma unroll
        for (int nt = 0; nt < 4; nt++) {
            int row0 = by * 128 + wm + mt * 16 + g;
            int col  = bx * 128 + wn + nt * 8 + 2 * tg;
            float bc0 = bias[col], bc1 = bias[col + 1];
            float v0 = acc[mt][nt][0] + bc0;
            float v1 = acc[mt][nt][1] + bc1;
            float v2 = acc[mt][nt][2] + bc0;
            float v3 = acc[mt][nt][3] + bc1;
            if (GELU) {
                v0 = 0.5f * v0 * (1.0f + erff(v0 * 0.70710678118654752f));
                v1 = 0.5f * v1 * (1.0f + erff(v1 * 0.70710678118654752f));
                v2 = 0.5f * v2 * (1.0f + erff(v2 * 0.70710678118654752f));
                v3 = 0.5f * v3 * (1.0f + erff(v3 * 0.70710678118654752f));
            }
            if (OUTH) {
                __half* Ch = (__half*)C;
                *(uint32_t*)(Ch + (size_t)row0 * N + col)       = pack_h2(v0, v1);
                *(uint32_t*)(Ch + (size_t)(row0 + 8) * N + col) = pack_h2(v2, v3);
            } else {
                float* Cf = (float*)C;
                *(float2*)(Cf + (size_t)row0 * N + col)       = make_float2(v0, v1);
                *(float2*)(Cf + (size_t)(row0 + 8) * N + col) = make_float2(v2, v3);
            }
        }
    }
}

// ---------------- naive head GEMM: out[M x 32] = h @ Wh + bh ----------------
__global__ void head_gemm_kernel(const float* __restrict__ h,
                                 const float* __restrict__ Wh,
                                 const float* __restrict__ bh,
                                 float* __restrict__ out) {
    int idx = blockIdx.x * blockDim.x + threadIdx.x;
    int n = idx & (PP - 1);
    int m = idx / PP;
    float acc = bh[n];
    const float* hp = h + (size_t)m * DD;
#pragma unroll 8
    for (int k = 0; k < DD; k++) acc += hp[k] * Wh[k * PP + n];
    out[idx] = acc;
}

// ---------------- residual add + LayerNorm (in-place into h) ----------------
__global__ void add_ln_kernel(float* __restrict__ h, const float* __restrict__ d,
                              const float* __restrict__ g, const float* __restrict__ b) {
    int row = blockIdx.x;
    int t   = threadIdx.x;
    float4 hv = *(float4*)(h + (size_t)row * DD + t * 4);
    float4 dv = *(const float4*)(d + (size_t)row * DD + t * 4);
    float v0 = hv.x + dv.x, v1 = hv.y + dv.y, v2 = hv.z + dv.z, v3 = hv.w + dv.w;
    float s  = v0 + v1 + v2 + v3;
    float s2 = v0 * v0 + v1 * v1 + v2 * v2 + v3 * v3;
#pragma unroll
    for (int off = 16; off; off >>= 1) {
        s  += __shfl_xor_sync(0xFFFFFFFF, s,  off);
        s2 += __shfl_xor_sync(0xFFFFFFFF, s2, off);
    }
    __shared__ float sh[8];
    int w = t >> 5, lane = t & 31;
    if (lane == 0) { sh[w] = s; sh[4 + w] = s2; }
    __syncthreads();
    s  = sh[0] + sh[1] + sh[2] + sh[3];
    s2 = sh[4] + sh[5] + sh[6] + sh[7];
    float mean = s * (1.0f / DD);
    float var  = s2 * (1.0f / DD) - mean * mean;
    float inv  = rsqrtf(var + 1e-5f);
    float4 gv = *(const float4*)(g + t * 4);
    float4 bv = *(const float4*)(b + t * 4);
    float4 o;
    o.x = (v0 - mean) * inv * gv.x + bv.x;
    o.y = (v1 - mean) * inv * gv.y + bv.y;
    o.z = (v2 - mean) * inv * gv.z + bv.z;
    o.w = (v3 - mean) * inv * gv.w + bv.w;
    *(float4*)(h + (size_t)row * DD + t * 4) = o;
}

// ---------------- fp16 tensor-core flash attention ---------------------------
// Block = 64 queries of one (b,h); 4 warps; warp tile 16q x 64keys.
// All tiles half, stride 72 halfs (frag banks 4g+tg, conflict-free).
// V fragments via ldmatrix.x2.trans from natural [key][d] layout.
#define HST 72

__global__ void __launch_bounds__(128)
attn4_kernel(const __half* __restrict__ q, const __half* __restrict__ k,
             const __half* __restrict__ v, const int* __restrict__ vids,
             const float* __restrict__ mask,
             const float* __restrict__ u_same, const float* __restrict__ u_cross,
             __half* __restrict__ o) {
    __shared__ __half Qs[64 * HST];
    __shared__ __half Ks[64 * HST];
    __shared__ __half Vs[64 * HST];
    __shared__ __half Ps[64 * HST];
    __shared__ int   svid[64];
    __shared__ float smask[64];

    const int tid  = threadIdx.x;
    const int warp = tid >> 5;
    const int lane = tid & 31;
    const int g    = lane >> 2;
    const int tg   = lane & 3;
    const int qw   = warp * 16;
    const int l16  = lane & 15;

    int qt = blockIdx.x & (SS / 64 - 1);
    int bh = blockIdx.x / (SS / 64);
    int hh = bh & (HH - 1);
    int b  = bh / HH;
    int q0 = qt * 64;

    const float us = u_same[hh], uc = u_cross[hh];

    // ---- stage Q ----
    {
        const __half* qbase = q + ((size_t)(b * SS + q0)) * DD + hh * HD;
#pragma unroll
        for (int r = 0; r < 4; r++) {
            int idx = tid + r * 128;
            int qi  = idx >> 3;
            int c8  = (idx & 7) * 8;
            *(uint4*)&Qs[qi * HST + c8] = *(const uint4*)(qbase + (size_t)qi * DD + c8);
        }
    }

    int vq0 = vids[b * SS + q0 + qw + g];
    int vq1 = vids[b * SS + q0 + qw + g + 8];
    float m0 = -1e30f, m1 = -1e30f, l0 = 0.0f, l1 = 0.0f;
    float oacc[8][4];
#pragma unroll
    for (int nt = 0; nt < 8; nt++)
#pragma unroll
        for (int r = 0; r < 4; r++) oacc[nt][r] = 0.0f;
    __syncthreads();

    for (int kt = 0; kt < SS; kt += 64) {
        // ---- stage K and V ----
        const __half* kbase = k + ((size_t)(b * SS + kt)) * DD + hh * HD;
        const __half* vbase = v + ((size_t)(b * SS + kt)) * DD + hh * HD;
#pragma unroll
        for (int r = 0; r < 4; r++) {
            int idx = tid + r * 128;
            int ki  = idx >> 3;
            int c8  = (idx & 7) * 8;
            *(uint4*)&Ks[ki * HST + c8] = *(const uint4*)(kbase + (size_t)ki * DD + c8);
            *(uint4*)&Vs[ki * HST + c8] = *(const uint4*)(vbase + (size_t)ki * DD + c8);
        }
        if (tid < 64) {
            svid[tid]  = vids[b * SS + kt + tid];
            smask[tid] = (1.0f - mask[b * SS + kt + tid]) * -1e9f;
        }
        __syncthreads();

        // ---- S = Q @ K^T ----
        float s[8][4];
#pragma unroll
        for (int nt = 0; nt < 8; nt++)
#pragma unroll
            for (int r = 0; r < 4; r++) s[nt][r] = 0.0f;
#pragma unroll
        for (int ks = 0; ks < 64; ks += 16) {
            uint32_t av[4];
            av[0] = *(const uint32_t*)&Qs[(qw + g)     * HST + ks + 2 * tg];
            av[1] = *(const uint32_t*)&Qs[(qw + g + 8) * HST + ks + 2 * tg];
            av[2] = *(const uint32_t*)&Qs[(qw + g)     * HST + ks + 2 * tg + 8];
            av[3] = *(const uint32_t*)&Qs[(qw + g + 8) * HST + ks + 2 * tg + 8];
#pragma unroll
            for (int nt = 0; nt < 8; nt++) {
                uint32_t bf[2];
                bf[0] = *(const uint32_t*)&Ks[(nt * 8 + g) * HST + ks + 2 * tg];
                bf[1] = *(const uint32_t*)&Ks[(nt * 8 + g) * HST + ks + 2 * tg + 8];
                mma_f16(s[nt], av, bf);
            }
        }

        // ---- bias + online softmax ----
        float rmax0 = -1e30f, rmax1 = -1e30f;
#pragma unroll
        for (int nt = 0; nt < 8; nt++) {
            int c0 = nt * 8 + 2 * tg;
            int c1 = c0 + 1;
            float bia0 = smask[c0], bia1 = smask[c1];
            s[nt][0] = s[nt][0] * 0.125f + (svid[c0] == vq0 ? us : uc) + bia0;
            s[nt][1] = s[nt][1] * 0.125f + (svid[c1] == vq0 ? us : uc) + bia1;
            s[nt][2] = s[nt][2] * 0.125f + (svid[c0] == vq1 ? us : uc) + bia0;
            s[nt][3] = s[nt][3] * 0.125f + (svid[c1] == vq1 ? us : uc) + bia1;
            rmax0 = fmaxf(rmax0, fmaxf(s[nt][0], s[nt][1]));
            rmax1 = fmaxf(rmax1, fmaxf(s[nt][2], s[nt][3]));
        }
        rmax0 = fmaxf(rmax0, __shfl_xor_sync(0xFFFFFFFF, rmax0, 1));
        rmax0 = fmaxf(rmax0, __shfl_xor_sync(0xFFFFFFFF, rmax0, 2));
        rmax1 = fmaxf(rmax1, __shfl_xor_sync(0xFFFFFFFF, rmax1, 1));
        rmax1 = fmaxf(rmax1, __shfl_xor_sync(0xFFFFFFFF, rmax1, 2));
        float newm0 = fmaxf(m0, rmax0);
        float newm1 = fmaxf(m1, rmax1);
        float corr0 = __expf(m0 - newm0);
        float corr1 = __expf(m1 - newm1);
        m0 = newm0; m1 = newm1;

        float rsum0 = 0.0f, rsum1 = 0.0f;
#pragma unroll
        for (int nt = 0; nt < 8; nt++) {
            float p0 = __expf(s[nt][0] - m0);
            float p1 = __expf(s[nt][1] - m0);
            float p2 = __expf(s[nt][2] - m1);
            float p3 = __expf(s[nt][3] - m1);
            rsum0 += p0 + p1;
            rsum1 += p2 + p3;
            int c0 = nt * 8 + 2 * tg;
            *(uint32_t*)&Ps[(qw + g)     * HST + c0] = pack_h2(p0, p1);
            *(uint32_t*)&Ps[(qw + g + 8) * HST + c0] = pack_h2(p2, p3);
            oacc[nt][0] *= corr0;
            oacc[nt][1] *= corr0;
            oacc[nt][2] *= corr1;
            oacc[nt][3] *= corr1;
        }
        rsum0 += __shfl_xor_sync(0xFFFFFFFF, rsum0, 1);
        rsum0 += __shfl_xor_sync(0xFFFFFFFF, rsum0, 2);
        rsum1 += __shfl_xor_sync(0xFFFFFFFF, rsum1, 1);
        rsum1 += __shfl_xor_sync(0xFFFFFFFF, rsum1, 2);
        l0 = l0 * corr0 + rsum0;
        l1 = l1 * corr1 + rsum1;
        __syncwarp();

        // ---- O += P @ V (V fragments via ldmatrix.trans) ----
#pragma unroll
        for (int ks = 0; ks < 64; ks += 16) {
            uint32_t av[4];
            av[0] = *(const uint32_t*)&Ps[(qw + g)     * HST + ks + 2 * tg];
            av[1] = *(const uint32_t*)&Ps[(qw + g + 8) * HST + ks + 2 * tg];
            av[2] = *(const uint32_t*)&Ps[(qw + g)     * HST + ks + 2 * tg + 8];
            av[3] = *(const uint32_t*)&Ps[(qw + g + 8) * HST + ks + 2 * tg + 8];
#pragma unroll
            for (int nt = 0; nt < 8; nt++) {
                uint32_t saddr = (uint32_t)__cvta_generic_to_shared(
                    &Vs[(ks + l16) * HST + nt * 8]);
                uint32_t bv0, bv1;
                ldmatrix_x2_trans(bv0, bv1, saddr);
                uint32_t bf[2] = {bv0, bv1};
                mma_f16(oacc[nt], av, bf);
            }
        }
        __syncthreads();
    }

    // ---- write O (half) ----
    float invl0 = 1.0f / l0;
    float invl1 = 1.0f / l1;
    __half* ob0 = o + ((size_t)(b * SS + q0 + qw + g)) * DD + hh * HD;
    __half* ob1 = ob0 + (size_t)8 * DD;
#pragma unroll
    for (int nt = 0; nt < 8; nt++) {
        int c = nt * 8 + 2 * tg;
        *(uint32_t*)(ob0 + c) = pack_h2(oacc[nt][0] * invl0, oacc[nt][1] * invl0);
        *(uint32_t*)(ob1 + c) = pack_h2(oacc[nt][2] * invl1, oacc[nt][3] * invl1);
    }
}

// ---------------- driver -----------------------------------------------------
extern "C" void kernel_launch(void* const* d_in, const int* in_sizes, int n_in,
                              void* d_out, int out_size) {
    const float* x      = (const float*)d_in[0];
    const int*   vids   = (const int*)  d_in[1];
    const float* mask   = (const float*)d_in[2];
    const float* W_pe   = (const float*)d_in[3];
    const float* b_pe   = (const float*)d_in[4];
    const float* Wq     = (const float*)d_in[5];
    const float* bq     = (const float*)d_in[6];
    const float* Wk     = (const float*)d_in[7];
    const float* bk     = (const float*)d_in[8];
    const float* Wv     = (const float*)d_in[9];
    const float* bv     = (const float*)d_in[10];
    const float* Wo     = (const float*)d_in[11];
    const float* bo     = (const float*)d_in[12];
    const float* u_same = (const float*)d_in[13];
    const float* u_cross= (const float*)d_in[14];
    const float* g1     = (const float*)d_in[15];
    const float* be1    = (const float*)d_in[16];
    const float* W1     = (const float*)d_in[17];
    const float* b1f    = (const float*)d_in[18];
    const float* W2     = (const float*)d_in[19];
    const float* b2f    = (const float*)d_in[20];
    const float* g2     = (const float*)d_in[21];
    const float* be2    = (const float*)d_in[22];
    const float* Wh     = (const float*)d_in[23];
    const float* bh     = (const float*)d_in[24];
    float* out = (float*)d_out;

    float *ph, *pt, *pc, *ps;
    __half *pq, *pk, *pv, *po, *pff;
    cudaGetSymbolAddress((void**)&ph,  g_h);
    cudaGetSymbolAddress((void**)&pt,  g_t);
    cudaGetSymbolAddress((void**)&pq,  g_qh);
    cudaGetSymbolAddress((void**)&pk,  g_kh);
    cudaGetSymbolAddress((void**)&pv,  g_vh);
    cudaGetSymbolAddress((void**)&po,  g_oh);
    cudaGetSymbolAddress((void**)&pff, g_ffh);
    cudaGetSymbolAddress((void**)&pc,  g_cos);
    cudaGetSymbolAddress((void**)&ps,  g_sin);

    rope_tables_kernel<<<(SS * 32 + 255) / 256, 256>>>(pc, ps);
    tgemm_bias<0, 0, 0><<<dim3(DD / 128, MM / 128), 256>>>(
        x, W_pe, W_pe, W_pe, b_pe, b_pe, b_pe, ph, ph, ph, MM, DD, PP, DD / 128);

    for (int l = 0; l < LL; l++) {
        const float* Wql = Wq + (size_t)l * DD * DD;
        const float* Wkl = Wk + (size_t)l * DD * DD;
        const float* Wvl = Wv + (size_t)l * DD * DD;
        const float* Wol = Wo + (size_t)l * DD * DD;
        const float* W1l = W1 + (size_t)l * DD * DF;
        const float* W2l = W2 + (size_t)l * DF * DD;

        // fused Q,K,V projection, half outputs
        tgemm_bias<0, 0, 1><<<dim3(3 * (DD / 128), MM / 128), 256>>>(
            ph, Wql, Wkl, Wvl, bq + l * DD, bk + l * DD, bv + l * DD,
            pq, pk, pv, MM, DD, DD, DD / 128);

        rope_apply_kernel<<<(2 * MM * HH * 32) / 256, 256>>>(pq, pk, pc, ps);

        attn4_kernel<<<BB * HH * (SS / 64), 128>>>(
            pq, pk, pv, vids, mask, u_same + l * HH, u_cross + l * HH, po);

        // Wo: half A input, float output
        tgemm_bias<0, 1, 0><<<dim3(DD / 128, MM / 128), 256>>>(
            po, Wol, Wol, Wol, bo + l * DD, bo + l * DD, bo + l * DD,
            pt, pt, pt, MM, DD, DD, DD / 128);
        add_ln_kernel<<<MM, 128>>>(ph, pt, g1 + l * DD, be1 + l * DD);

        // FFN: W1 half out (GELU), W2 half in, float out
        tgemm_bias<1, 0, 1><<<dim3(DF / 128, MM / 128), 256>>>(
            ph, W1l, W1l, W1l, b1f + l * DF, b1f + l * DF, b1f + l * DF,
            pff, pff, pff, MM, DF, DD, DF / 128);
        tgemm_bias<0, 1, 0><<<dim3(DD / 128, MM / 128), 256>>>(
            pff, W2l, W2l, W2l, b2f + l * DD, b2f + l * DD, b2f + l * DD,
            pt, pt, pt, MM, DD, DF, DD / 128);
        add_ln_kernel<<<MM, 128>>>(ph, pt, g2 + l * DD, be2 + l * DD);
    }

    head_gemm_kernel<<<(MM * PP) / 256, 256>>>(ph, Wh, bh, out);
}

// round 9
// speedup vs baseline: 1.7163x; 1.1034x over previous
#include <cuda_runtime.h>
#include <cuda_fp16.h>
#include <math.h>
#include <stdint.h>

#define BB  4
#define SS  2048
#define PP  32
#define DD  512
#define HH  8
#define LL  2
#define DF  2048
#define HD  64
#define MM  (BB*SS)   /* 8192 rows */

// ---------------- scratch (device globals; no allocations allowed) ----------
__device__ float  g_h [MM*DD];
__device__ float  g_t [MM*DD];
__device__ __half g_qh [MM*DD];
__device__ __half g_kh [MM*DD];
__device__ __half g_vh [MM*DD];
__device__ __half g_oh [MM*DD];
__device__ __half g_ffh[MM*DF];
__device__ float  g_cos[SS*32];
__device__ float  g_sin[SS*32];

// ---------------- fp16 helpers ----------------------------------------------
__device__ __forceinline__ void mma_f16(float* c, const uint32_t* a, const uint32_t* b) {
    asm volatile(
        "mma.sync.aligned.m16n8k16.row.col.f32.f16.f16.f32 "
        "{%0,%1,%2,%3}, {%4,%5,%6,%7}, {%8,%9}, {%0,%1,%2,%3};\n"
        : "+f"(c[0]), "+f"(c[1]), "+f"(c[2]), "+f"(c[3])
        : "r"(a[0]), "r"(a[1]), "r"(a[2]), "r"(a[3]), "r"(b[0]), "r"(b[1]));
}

__device__ __forceinline__ uint32_t pack_h2(float lo, float hi) {
    __half2 h = __floats2half2_rn(lo, hi);
    return *(uint32_t*)&h;
}

__device__ __forceinline__ void ldmatrix_x4(uint32_t* r, uint32_t saddr) {
    asm volatile("ldmatrix.sync.aligned.m8n8.x4.shared.b16 {%0,%1,%2,%3}, [%4];"
                 : "=r"(r[0]), "=r"(r[1]), "=r"(r[2]), "=r"(r[3]) : "r"(saddr));
}

__device__ __forceinline__ void ldmatrix_x4_trans(uint32_t* r, uint32_t saddr) {
    asm volatile("ldmatrix.sync.aligned.m8n8.x4.trans.shared.b16 {%0,%1,%2,%3}, [%4];"
                 : "=r"(r[0]), "=r"(r[1]), "=r"(r[2]), "=r"(r[3]) : "r"(saddr));
}

// ---------------- RoPE tables ----------------------------------------------
__global__ void rope_tables_kernel(float* __restrict__ ct, float* __restrict__ st) {
    int idx = blockIdx.x * blockDim.x + threadIdx.x;
    if (idx >= SS * 32) return;
    int pos = idx >> 5;
    int i   = idx & 31;
    int fidx = (2 * i) & 31;
    float ex  = (float)(2 * fidx) / 64.0f;
    float inv = 1.0f / powf(10000.0f, ex);
    float ang = (float)pos * inv;
    ct[idx] = cosf(ang);
    st[idx] = sinf(ang);
}

// one launch applies RoPE to both q and k (half storage, fp32 math)
__global__ void rope_apply_kernel(__half* __restrict__ q, __half* __restrict__ k,
                                  const float* __restrict__ ct,
                                  const float* __restrict__ st) {
    int gidx = blockIdx.x * blockDim.x + threadIdx.x;   // 2*MM*HH*32 threads
    __half* base = (gidx < MM * HH * 32) ? q : k;
    int idx = (gidx < MM * HH * 32) ? gidx : gidx - MM * HH * 32;
    int i   = idx & 31;
    int rem = idx >> 5;
    int hh  = rem & (HH - 1);
    int row = rem >> 3;
    int s   = row & (SS - 1);
    float c  = ct[s * 32 + i];
    float sn = st[s * 32 + i];
    __half2* p = (__half2*)(base + (size_t)row * DD + hh * HD + 2 * i);
    float2 x = __half22float2(*p);
    *p = __floats2half2_rn(x.x * c - x.y * sn, x.x * sn + x.y * c);
}

// ---------------- FP16 tensor-core GEMM --------------------------------------
// C = A[MxK] @ Bsel[KxN] + bias_sel. A fp32 or fp16 (INH), C fp32 or fp16 (OUTH).
// Block 128x128x16, 8 warps (2M x 4N), warp tile 64x32, mma.m16n8k16.f16,
// double-buffered, fragments via ldmatrix.x4.
#define AST 24
#define KST 24

template <int GELU, int INH, int OUTH>
__global__ void __launch_bounds__(256)
tgemm_bias(const void* __restrict__ A_,
           const float* __restrict__ B0, const float* __restrict__ B1,
           const float* __restrict__ B2,
           const float* __restrict__ bias0, const float* __restrict__ bias1,
           const float* __restrict__ bias2,
           void* __restrict__ C0, void* __restrict__ C1, void* __restrict__ C2,
           int M, int N, int K, int ntile) {
    __shared__ __half As[2][128 * AST];
    __shared__ __half Bs[2][128 * KST];

    const int sel = blockIdx.x / ntile;
    const int bx  = blockIdx.x - sel * ntile;
    const int by  = blockIdx.y;
    const float* B    = (sel == 0) ? B0 : (sel == 1) ? B1 : B2;
    const float* bias = (sel == 0) ? bias0 : (sel == 1) ? bias1 : bias2;
    void*        C    = (sel == 0) ? C0 : (sel == 1) ? C1 : C2;

    const int tid  = threadIdx.x;
    const int warp = tid >> 5;
    const int lane = tid & 31;
    const int g    = lane >> 2;
    const int tg   = lane & 3;
    const int wm   = (warp & 1) * 64;
    const int wn   = (warp >> 1) * 32;

    const int aRow = tid >> 1;
    const int aK0  = (tid & 1) * 8;
    const int bN  = tid & 127;
    const int bKh = (tid >> 7) * 8;

    // ldmatrix lane-address components
    const int lmARowOff = (lane & 7) + ((lane >> 3) & 1) * 8;  // row within 16
    const int lmAColOff = (lane >> 4) * 8;                     // k chunk
    const int lmBRowOff = (lane & 7) + ((lane >> 4) & 1) * 8;  // n within 16
    const int lmBColOff = ((lane >> 3) & 1) * 8;               // k chunk

    const float*  Apf = (const float*)A_  + (size_t)(by * 128 + aRow) * K + aK0;
    const __half* Aph = (const __half*)A_ + (size_t)(by * 128 + aRow) * K + aK0;
    const float*  Bp  = B + (size_t)bKh * N + bx * 128 + bN;

    float acc[4][4][4];
#pragma unroll
    for (int i = 0; i < 4; i++)
#pragma unroll
        for (int j = 0; j < 4; j++)
#pragma unroll
            for (int r = 0; r < 4; r++) acc[i][j][r] = 0.0f;

    uint4 apack;
    float bR[8];

    // prefetch stage 0
    if (INH) {
        apack = *(const uint4*)Aph;  Aph += 16;
    } else {
        float4 a0 = *(const float4*)(Apf);
        float4 a1 = *(const float4*)(Apf + 4);
        apack = make_uint4(pack_h2(a0.x, a0.y), pack_h2(a0.z, a0.w),
                           pack_h2(a1.x, a1.y), pack_h2(a1.z, a1.w));
        Apf += 16;
    }
#pragma unroll
    for (int j = 0; j < 8; j++) bR[j] = Bp[(size_t)j * N];
    Bp += (size_t)16 * N;

    // store stage 0
    *(uint4*)&As[0][aRow * AST + aK0] = apack;
    *(uint4*)&Bs[0][bN * KST + bKh] =
        make_uint4(pack_h2(bR[0], bR[1]), pack_h2(bR[2], bR[3]),
                   pack_h2(bR[4], bR[5]), pack_h2(bR[6], bR[7]));
    __syncthreads();

    const int nIter = K >> 4;
    for (int it = 0; it < nIter; it++) {
        const int buf = it & 1;
        const bool more = (it + 1 < nIter);

        if (more) {
            if (INH) {
                apack = *(const uint4*)Aph;  Aph += 16;
            } else {
                float4 a0 = *(const float4*)(Apf);
                float4 a1 = *(const float4*)(Apf + 4);
                apack = make_uint4(pack_h2(a0.x, a0.y), pack_h2(a0.z, a0.w),
                                   pack_h2(a1.x, a1.y), pack_h2(a1.z, a1.w));
                Apf += 16;
            }
#pragma unroll
            for (int j = 0; j < 8; j++) bR[j] = Bp[(size_t)j * N];
            Bp += (size_t)16 * N;
        }

        {
            const uint32_t asBase = (uint32_t)__cvta_generic_to_shared(&As[buf][0]);
            const uint32_t bsBase = (uint32_t)__cvta_generic_to_shared(&Bs[buf][0]);
            uint32_t af[4][4], bf[4][4];
#pragma unroll
            for (int mt = 0; mt < 4; mt++) {
                int arow = wm + mt * 16 + lmARowOff;
                ldmatrix_x4(af[mt], asBase + (arow * AST + lmAColOff) * 2);
            }
#pragma unroll
            for (int p = 0; p < 2; p++) {
                int n = wn + p * 16 + lmBRowOff;
                ldmatrix_x4(bf[p * 2], bsBase + (n * KST + lmBColOff) * 2);
                bf[p * 2 + 1][0] = bf[p * 2][2];
                bf[p * 2 + 1][1] = bf[p * 2][3];
            }
#pragma unroll
            for (int mt = 0; mt < 4; mt++)
#pragma unroll
                for (int nt = 0; nt < 4; nt++)
                    mma_f16(acc[mt][nt], af[mt], bf[nt]);
        }

        if (more) {
            int nb = buf ^ 1;
            *(uint4*)&As[nb][aRow * AST + aK0] = apack;
            *(uint4*)&Bs[nb][bN * KST + bKh] =
                make_uint4(pack_h2(bR[0], bR[1]), pack_h2(bR[2], bR[3]),
                           pack_h2(bR[4], bR[5]), pack_h2(bR[6], bR[7]));
            __syncthreads();
        }
    }

    // epilogue: bias (+GELU)
#pragma unroll
    for (int mt = 0; mt < 4; mt++) {
#pragma unroll
        for (int nt = 0; nt < 4; nt++) {
            int row0 = by * 128 + wm + mt * 16 + g;
            int col  = bx * 128 + wn + nt * 8 + 2 * tg;
            float bc0 = bias[col], bc1 = bias[col + 1];
            float v0 = acc[mt][nt][0] + bc0;
            float v1 = acc[mt][nt][1] + bc1;
            float v2 = acc[mt][nt][2] + bc0;
            float v3 = acc[mt][nt][3] + bc1;
            if (GELU) {
                v0 = 0.5f * v0 * (1.0f + erff(v0 * 0.70710678118654752f));
                v1 = 0.5f * v1 * (1.0f + erff(v1 * 0.70710678118654752f));
                v2 = 0.5f * v2 * (1.0f + erff(v2 * 0.70710678118654752f));
                v3 = 0.5f * v3 * (1.0f + erff(v3 * 0.70710678118654752f));
            }
            if (OUTH) {
                __half* Ch = (__half*)C;
                *(uint32_t*)(Ch + (size_t)row0 * N + col)       = pack_h2(v0, v1);
                *(uint32_t*)(Ch + (size_t)(row0 + 8) * N + col) = pack_h2(v2, v3);
            } else {
                float* Cf = (float*)C;
                *(float2*)(Cf + (size_t)row0 * N + col)       = make_float2(v0, v1);
                *(float2*)(Cf + (size_t)(row0 + 8) * N + col) = make_float2(v2, v3);
            }
        }
    }
}

// ---------------- naive head GEMM: out[M x 32] = h @ Wh + bh ----------------
__global__ void head_gemm_kernel(const float* __restrict__ h,
                                 const float* __restrict__ Wh,
                                 const float* __restrict__ bh,
                                 float* __restrict__ out) {
    int idx = blockIdx.x * blockDim.x + threadIdx.x;
    int n = idx & (PP - 1);
    int m = idx / PP;
    float acc = bh[n];
    const float* hp = h + (size_t)m * DD;
#pragma unroll 8
    for (int k = 0; k < DD; k++) acc += hp[k] * Wh[k * PP + n];
    out[idx] = acc;
}

// ---------------- residual add + LayerNorm (in-place into h) ----------------
__global__ void add_ln_kernel(float* __restrict__ h, const float* __restrict__ d,
                              const float* __restrict__ g, const float* __restrict__ b) {
    int row = blockIdx.x;
    int t   = threadIdx.x;
    float4 hv = *(float4*)(h + (size_t)row * DD + t * 4);
    float4 dv = *(const float4*)(d + (size_t)row * DD + t * 4);
    float v0 = hv.x + dv.x, v1 = hv.y + dv.y, v2 = hv.z + dv.z, v3 = hv.w + dv.w;
    float s  = v0 + v1 + v2 + v3;
    float s2 = v0 * v0 + v1 * v1 + v2 * v2 + v3 * v3;
#pragma unroll
    for (int off = 16; off; off >>= 1) {
        s  += __shfl_xor_sync(0xFFFFFFFF, s,  off);
        s2 += __shfl_xor_sync(0xFFFFFFFF, s2, off);
    }
    __shared__ float sh[8];
    int w = t >> 5, lane = t & 31;
    if (lane == 0) { sh[w] = s; sh[4 + w] = s2; }
    __syncthreads();
    s  = sh[0] + sh[1] + sh[2] + sh[3];
    s2 = sh[4] + sh[5] + sh[6] + sh[7];
    float mean = s * (1.0f / DD);
    float var  = s2 * (1.0f / DD) - mean * mean;
    float inv  = rsqrtf(var + 1e-5f);
    float4 gv = *(const float4*)(g + t * 4);
    float4 bv = *(const float4*)(b + t * 4);
    float4 o;
    o.x = (v0 - mean) * inv * gv.x + bv.x;
    o.y = (v1 - mean) * inv * gv.y + bv.y;
    o.z = (v2 - mean) * inv * gv.z + bv.z;
    o.w = (v3 - mean) * inv * gv.w + bv.w;
    *(float4*)(h + (size_t)row * DD + t * 4) = o;
}

// ---------------- fp16 tensor-core flash attention ---------------------------
// Block = 64 queries of one (b,h); 4 warps; warp tile 16q x 64keys.
// Fragments via ldmatrix.x4; V via ldmatrix.x4.trans.
#define HST 72

__global__ void __launch_bounds__(128)
attn4_kernel(const __half* __restrict__ q, const __half* __restrict__ k,
             const __half* __restrict__ v, const int* __restrict__ vids,
             const float* __restrict__ mask,
             const float* __restrict__ u_same, const float* __restrict__ u_cross,
             __half* __restrict__ o) {
    __shared__ __half Qs[64 * HST];
    __shared__ __half Ks[64 * HST];
    __shared__ __half Vs[64 * HST];
    __shared__ __half Ps[64 * HST];
    __shared__ int   svid[64];
    __shared__ float smask[64];

    const int tid  = threadIdx.x;
    const int warp = tid >> 5;
    const int lane = tid & 31;
    const int g    = lane >> 2;
    const int tg   = lane & 3;
    const int qw   = warp * 16;

    const int lmARowOff = (lane & 7) + ((lane >> 3) & 1) * 8;
    const int lmAColOff = (lane >> 4) * 8;
    const int lmBRowOff = (lane & 7) + ((lane >> 4) & 1) * 8;
    const int lmBColOff = ((lane >> 3) & 1) * 8;
    const int lmVRow    = lane & 15;
    const int lmVColOff = (lane >> 4) * 8;

    int qt = blockIdx.x & (SS / 64 - 1);
    int bh = blockIdx.x / (SS / 64);
    int hh = bh & (HH - 1);
    int b  = bh / HH;
    int q0 = qt * 64;

    const float us = u_same[hh], uc = u_cross[hh];

    const uint32_t qsBase = (uint32_t)__cvta_generic_to_shared(Qs);
    const uint32_t ksBase = (uint32_t)__cvta_generic_to_shared(Ks);
    const uint32_t vsBase = (uint32_t)__cvta_generic_to_shared(Vs);
    const uint32_t psBase = (uint32_t)__cvta_generic_to_shared(Ps);

    // ---- stage Q ----
    {
        const __half* qbase = q + ((size_t)(b * SS + q0)) * DD + hh * HD;
#pragma unroll
        for (int r = 0; r < 4; r++) {
            int idx = tid + r * 128;
            int qi  = idx >> 3;
            int c8  = (idx & 7) * 8;
            *(uint4*)&Qs[qi * HST + c8] = *(const uint4*)(qbase + (size_t)qi * DD + c8);
        }
    }

    int vq0 = vids[b * SS + q0 + qw + g];
    int vq1 = vids[b * SS + q0 + qw + g + 8];
    float m0 = -1e30f, m1 = -1e30f, l0 = 0.0f, l1 = 0.0f;
    float oacc[8][4];
#pragma unroll
    for (int nt = 0; nt < 8; nt++)
#pragma unroll
        for (int r = 0; r < 4; r++) oacc[nt][r] = 0.0f;
    __syncthreads();

    for (int kt = 0; kt < SS; kt += 64) {
        // ---- stage K and V ----
        const __half* kbase = k + ((size_t)(b * SS + kt)) * DD + hh * HD;
        const __half* vbase = v + ((size_t)(b * SS + kt)) * DD + hh * HD;
#pragma unroll
        for (int r = 0; r < 4; r++) {
            int idx = tid + r * 128;
            int ki  = idx >> 3;
            int c8  = (idx & 7) * 8;
            *(uint4*)&Ks[ki * HST + c8] = *(const uint4*)(kbase + (size_t)ki * DD + c8);
            *(uint4*)&Vs[ki * HST + c8] = *(const uint4*)(vbase + (size_t)ki * DD + c8);
        }
        if (tid < 64) {
            svid[tid]  = vids[b * SS + kt + tid];
            smask[tid] = (1.0f - mask[b * SS + kt + tid]) * -1e9f;
        }
        __syncthreads();

        // ---- S = Q @ K^T ----
        float s[8][4];
#pragma unroll
        for (int nt = 0; nt < 8; nt++)
#pragma unroll
            for (int r = 0; r < 4; r++) s[nt][r] = 0.0f;
#pragma unroll
        for (int ks = 0; ks < 64; ks += 16) {
            uint32_t av[4];
            ldmatrix_x4(av, qsBase + ((qw + lmARowOff) * HST + ks + lmAColOff) * 2);
#pragma unroll
            for (int p = 0; p < 4; p++) {
                uint32_t r[4];
                int n = p * 16 + lmBRowOff;
                ldmatrix_x4(r, ksBase + (n * HST + ks + lmBColOff) * 2);
                mma_f16(s[2 * p],     av, r);
                mma_f16(s[2 * p + 1], av, r + 2);
            }
        }

        // ---- bias + online softmax ----
        float rmax0 = -1e30f, rmax1 = -1e30f;
#pragma unroll
        for (int nt = 0; nt < 8; nt++) {
            int c0 = nt * 8 + 2 * tg;
            int c1 = c0 + 1;
            float bia0 = smask[c0], bia1 = smask[c1];
            s[nt][0] = s[nt][0] * 0.125f + (svid[c0] == vq0 ? us : uc) + bia0;
            s[nt][1] = s[nt][1] * 0.125f + (svid[c1] == vq0 ? us : uc) + bia1;
            s[nt][2] = s[nt][2] * 0.125f + (svid[c0] == vq1 ? us : uc) + bia0;
            s[nt][3] = s[nt][3] * 0.125f + (svid[c1] == vq1 ? us : uc) + bia1;
            rmax0 = fmaxf(rmax0, fmaxf(s[nt][0], s[nt][1]));
            rmax1 = fmaxf(rmax1, fmaxf(s[nt][2], s[nt][3]));
        }
        rmax0 = fmaxf(rmax0, __shfl_xor_sync(0xFFFFFFFF, rmax0, 1));
        rmax0 = fmaxf(rmax0, __shfl_xor_sync(0xFFFFFFFF, rmax0, 2));
        rmax1 = fmaxf(rmax1, __shfl_xor_sync(0xFFFFFFFF, rmax1, 1));
        rmax1 = fmaxf(rmax1, __shfl_xor_sync(0xFFFFFFFF, rmax1, 2));
        float newm0 = fmaxf(m0, rmax0);
        float newm1 = fmaxf(m1, rmax1);
        float corr0 = __expf(m0 - newm0);
        float corr1 = __expf(m1 - newm1);
        m0 = newm0; m1 = newm1;

        float rsum0 = 0.0f, rsum1 = 0.0f;
#pragma unroll
        for (int nt = 0; nt < 8; nt++) {
            float p0 = __expf(s[nt][0] - m0);
            float p1 = __expf(s[nt][1] - m0);
            float p2 = __expf(s[nt][2] - m1);
            float p3 = __expf(s[nt][3] - m1);
            rsum0 += p0 + p1;
            rsum1 += p2 + p3;
            int c0 = nt * 8 + 2 * tg;
            *(uint32_t*)&Ps[(qw + g)     * HST + c0] = pack_h2(p0, p1);
            *(uint32_t*)&Ps[(qw + g + 8) * HST + c0] = pack_h2(p2, p3);
            oacc[nt][0] *= corr0;
            oacc[nt][1] *= corr0;
            oacc[nt][2] *= corr1;
            oacc[nt][3] *= corr1;
        }
        rsum0 += __shfl_xor_sync(0xFFFFFFFF, rsum0, 1);
        rsum0 += __shfl_xor_sync(0xFFFFFFFF, rsum0, 2);
        rsum1 += __shfl_xor_sync(0xFFFFFFFF, rsum1, 1);
        rsum1 += __shfl_xor_sync(0xFFFFFFFF, rsum1, 2);
        l0 = l0 * corr0 + rsum0;
        l1 = l1 * corr1 + rsum1;
        __syncwarp();

        // ---- O += P @ V ----
#pragma unroll
        for (int ks = 0; ks < 64; ks += 16) {
            uint32_t av[4];
            ldmatrix_x4(av, psBase + ((qw + lmARowOff) * HST + ks + lmAColOff) * 2);
#pragma unroll
            for (int p = 0; p < 4; p++) {
                uint32_t r[4];
                int col = p * 16 + lmVColOff;
                ldmatrix_x4_trans(r, vsBase + ((ks + lmVRow) * HST + col) * 2);
                mma_f16(oacc[2 * p],     av, r);
                mma_f16(oacc[2 * p + 1], av, r + 2);
            }
        }
        __syncthreads();
    }

    // ---- write O (half) ----
    float invl0 = 1.0f / l0;
    float invl1 = 1.0f / l1;
    __half* ob0 = o + ((size_t)(b * SS + q0 + qw + g)) * DD + hh * HD;
    __half* ob1 = ob0 + (size_t)8 * DD;
#pragma unroll
    for (int nt = 0; nt < 8; nt++) {
        int c = nt * 8 + 2 * tg;
        *(uint32_t*)(ob0 + c) = pack_h2(oacc[nt][0] * invl0, oacc[nt][1] * invl0);
        *(uint32_t*)(ob1 + c) = pack_h2(oacc[nt][2] * invl1, oacc[nt][3] * invl1);
    }
}

// ---------------- driver -----------------------------------------------------
extern "C" void kernel_launch(void* const* d_in, const int* in_sizes, int n_in,
                              void* d_out, int out_size) {
    const float* x      = (const float*)d_in[0];
    const int*   vids   = (const int*)  d_in[1];
    const float* mask   = (const float*)d_in[2];
    const float* W_pe   = (const float*)d_in[3];
    const float* b_pe   = (const float*)d_in[4];
    const float* Wq     = (const float*)d_in[5];
    const float* bq     = (const float*)d_in[6];
    const float* Wk     = (const float*)d_in[7];
    const float* bk     = (const float*)d_in[8];
    const float* Wv     = (const float*)d_in[9];
    const float* bv     = (const float*)d_in[10];
    const float* Wo     = (const float*)d_in[11];
    const float* bo     = (const float*)d_in[12];
    const float* u_same = (const float*)d_in[13];
    const float* u_cross= (const float*)d_in[14];
    const float* g1     = (const float*)d_in[15];
    const float* be1    = (const float*)d_in[16];
    const float* W1     = (const float*)d_in[17];
    const float* b1f    = (const float*)d_in[18];
    const float* W2     = (const float*)d_in[19];
    const float* b2f    = (const float*)d_in[20];
    const float* g2     = (const float*)d_in[21];
    const float* be2    = (const float*)d_in[22];
    const float* Wh     = (const float*)d_in[23];
    const float* bh     = (const float*)d_in[24];
    float* out = (float*)d_out;

    float *ph, *pt, *pc, *ps;
    __half *pq, *pk, *pv, *po, *pff;
    cudaGetSymbolAddress((void**)&ph,  g_h);
    cudaGetSymbolAddress((void**)&pt,  g_t);
    cudaGetSymbolAddress((void**)&pq,  g_qh);
    cudaGetSymbolAddress((void**)&pk,  g_kh);
    cudaGetSymbolAddress((void**)&pv,  g_vh);
    cudaGetSymbolAddress((void**)&po,  g_oh);
    cudaGetSymbolAddress((void**)&pff, g_ffh);
    cudaGetSymbolAddress((void**)&pc,  g_cos);
    cudaGetSymbolAddress((void**)&ps,  g_sin);

    rope_tables_kernel<<<(SS * 32 + 255) / 256, 256>>>(pc, ps);
    tgemm_bias<0, 0, 0><<<dim3(DD / 128, MM / 128), 256>>>(
        x, W_pe, W_pe, W_pe, b_pe, b_pe, b_pe, ph, ph, ph, MM, DD, PP, DD / 128);

    for (int l = 0; l < LL; l++) {
        const float* Wql = Wq + (size_t)l * DD * DD;
        const float* Wkl = Wk + (size_t)l * DD * DD;
        const float* Wvl = Wv + (size_t)l * DD * DD;
        const float* Wol = Wo + (size_t)l * DD * DD;
        const float* W1l = W1 + (size_t)l * DD * DF;
        const float* W2l = W2 + (size_t)l * DF * DD;

        tgemm_bias<0, 0, 1><<<dim3(3 * (DD / 128), MM / 128), 256>>>(
            ph, Wql, Wkl, Wvl, bq + l * DD, bk + l * DD, bv + l * DD,
            pq, pk, pv, MM, DD, DD, DD / 128);

        rope_apply_kernel<<<(2 * MM * HH * 32) / 256, 256>>>(pq, pk, pc, ps);

        attn4_kernel<<<BB * HH * (SS / 64), 128>>>(
            pq, pk, pv, vids, mask, u_same + l * HH, u_cross + l * HH, po);

        tgemm_bias<0, 1, 0><<<dim3(DD / 128, MM / 128), 256>>>(
            po, Wol, Wol, Wol, bo + l * DD, bo + l * DD, bo + l * DD,
            pt, pt, pt, MM, DD, DD, DD / 128);
        add_ln_kernel<<<MM, 128>>>(ph, pt, g1 + l * DD, be1 + l * DD);

        tgemm_bias<1, 0, 1><<<dim3(DF / 128, MM / 128), 256>>>(
            ph, W1l, W1l, W1l, b1f + l * DF, b1f + l * DF, b1f + l * DF,
            pff, pff, pff, MM, DF, DD, DF / 128);
        tgemm_bias<0, 1, 0><<<dim3(DD / 128, MM / 128), 256>>>(
            pff, W2l, W2l, W2l, b2f + l * DD, b2f + l * DD, b2f + l * DD,
            pt, pt, pt, MM, DD, DF, DD / 128);
        add_ln_kernel<<<MM, 128>>>(ph, pt, g2 + l * DD, be2 + l * DD);
    }

    head_gemm_kernel<<<(MM * PP) / 256, 256>>>(ph, Wh, bh, out);
}

// round 10
// speedup vs baseline: 1.8370x; 1.0703x over previous
#include <cuda_runtime.h>
#include <cuda_fp16.h>
#include <math.h>
#include <stdint.h>

#define BB  4
#define SS  2048
#define PP  32
#define DD  512
#define HH  8
#define LL  2
#define DF  2048
#define HD  64
#define MM  (BB*SS)   /* 8192 rows */

// half-weight buffer offsets (element counts)
#define S_W   (DD*DD)
#define S_W1  (DD*DF)
#define OFF_WPE 0
#define OFF_WQ  (PP*DD)
#define OFF_WK  (OFF_WQ + LL*S_W)
#define OFF_WV  (OFF_WK + LL*S_W)
#define OFF_WO  (OFF_WV + LL*S_W)
#define OFF_W1  (OFF_WO + LL*S_W)
#define OFF_W2  (OFF_W1 + LL*S_W1)
#define TOTAL_W (OFF_W2 + LL*S_W1)
#define NX      (MM*PP)

// ---------------- scratch (device globals; no allocations allowed) ----------
__device__ float  g_h [MM*DD];
__device__ float  g_t [MM*DD];
__device__ __half g_hh [MM*DD];
__device__ __half g_qh [MM*DD];
__device__ __half g_kh [MM*DD];
__device__ __half g_vh [MM*DD];
__device__ __half g_oh [MM*DD];
__device__ __half g_ffh[MM*DF];
__device__ __half g_xh [NX];
__device__ __half g_wh [TOTAL_W];
__device__ float  g_cos[SS*32];
__device__ float  g_sin[SS*32];

// ---------------- fp16 helpers ----------------------------------------------
__device__ __forceinline__ void mma_f16(float* c, const uint32_t* a, const uint32_t* b) {
    asm volatile(
        "mma.sync.aligned.m16n8k16.row.col.f32.f16.f16.f32 "
        "{%0,%1,%2,%3}, {%4,%5,%6,%7}, {%8,%9}, {%0,%1,%2,%3};\n"
        : "+f"(c[0]), "+f"(c[1]), "+f"(c[2]), "+f"(c[3])
        : "r"(a[0]), "r"(a[1]), "r"(a[2]), "r"(a[3]), "r"(b[0]), "r"(b[1]));
}

__device__ __forceinline__ uint32_t pack_h2(float lo, float hi) {
    __half2 h = __floats2half2_rn(lo, hi);
    return *(uint32_t*)&h;
}

__device__ __forceinline__ void ldmatrix_x4(uint32_t* r, uint32_t saddr) {
    asm volatile("ldmatrix.sync.aligned.m8n8.x4.shared.b16 {%0,%1,%2,%3}, [%4];"
                 : "=r"(r[0]), "=r"(r[1]), "=r"(r[2]), "=r"(r[3]) : "r"(saddr));
}

__device__ __forceinline__ void ldmatrix_x4_trans(uint32_t* r, uint32_t saddr) {
    asm volatile("ldmatrix.sync.aligned.m8n8.x4.trans.shared.b16 {%0,%1,%2,%3}, [%4];"
                 : "=r"(r[0]), "=r"(r[1]), "=r"(r[2]), "=r"(r[3]) : "r"(saddr));
}

// ---------------- fp32 -> fp16 conversion of x + all weights ----------------
__global__ void convert_kernel(const float* __restrict__ x,
                               const float* __restrict__ wpe,
                               const float* __restrict__ wq, const float* __restrict__ wk,
                               const float* __restrict__ wv, const float* __restrict__ wo,
                               const float* __restrict__ w1, const float* __restrict__ w2,
                               __half* __restrict__ xh, __half* __restrict__ wh) {
    int idx = blockIdx.x * blockDim.x + threadIdx.x;
    if (idx < NX) { xh[idx] = __float2half(x[idx]); return; }
    int j = idx - NX;
    if (j >= TOTAL_W) return;
    const float* src;
    int off;
    if      (j < OFF_WQ) { src = wpe; off = OFF_WPE; }
    else if (j < OFF_WK) { src = wq;  off = OFF_WQ; }
    else if (j < OFF_WV) { src = wk;  off = OFF_WK; }
    else if (j < OFF_WO) { src = wv;  off = OFF_WV; }
    else if (j < OFF_W1) { src = wo;  off = OFF_WO; }
    else if (j < OFF_W2) { src = w1;  off = OFF_W1; }
    else                 { src = w2;  off = OFF_W2; }
    wh[j] = __float2half(src[j - off]);
}

// ---------------- RoPE tables ----------------------------------------------
__global__ void rope_tables_kernel(float* __restrict__ ct, float* __restrict__ st) {
    int idx = blockIdx.x * blockDim.x + threadIdx.x;
    if (idx >= SS * 32) return;
    int pos = idx >> 5;
    int i   = idx & 31;
    int fidx = (2 * i) & 31;
    float ex  = (float)(2 * fidx) / 64.0f;
    float inv = 1.0f / powf(10000.0f, ex);
    float ang = (float)pos * inv;
    ct[idx] = cosf(ang);
    st[idx] = sinf(ang);
}

// ---------------- FP16 tensor-core GEMM --------------------------------------
// C = A[MxK](half) @ Bsel[KxN](half) + bias_sel.
// OUTH: 0=float out, 1=half out, 2=float C + half Cdual.
// ROPE: rotate output pairs for sel 0,1 (Q,K projections).
// Block 128x128x16, 8 warps (2M x 4N), warp tile 64x32, ldmatrix everywhere.
#define AST 24
#define BSN 136

template <int GELU, int ROPE, int OUTH>
__global__ void __launch_bounds__(256)
tgemm_bias(const __half* __restrict__ A,
           const __half* __restrict__ B0, const __half* __restrict__ B1,
           const __half* __restrict__ B2,
           const float* __restrict__ bias0, const float* __restrict__ bias1,
           const float* __restrict__ bias2,
           void* __restrict__ C0, void* __restrict__ C1, void* __restrict__ C2,
           __half* __restrict__ Cdual,
           const float* __restrict__ ct, const float* __restrict__ st,
           int M, int N, int K, int ntile) {
    __shared__ __half As[2][128 * AST];
    __shared__ __half Bs[2][16 * BSN];

    const int sel = blockIdx.x / ntile;
    const int bx  = blockIdx.x - sel * ntile;
    const int by  = blockIdx.y;
    const __half* B    = (sel == 0) ? B0 : (sel == 1) ? B1 : B2;
    const float*  bias = (sel == 0) ? bias0 : (sel == 1) ? bias1 : bias2;
    void*         C    = (sel == 0) ? C0 : (sel == 1) ? C1 : C2;

    const int tid  = threadIdx.x;
    const int warp = tid >> 5;
    const int lane = tid & 31;
    const int g    = lane >> 2;
    const int tg   = lane & 3;
    const int wm   = (warp & 1) * 64;
    const int wn   = (warp >> 1) * 32;

    // staging coords
    const int aRow = tid >> 1;
    const int aK0  = (tid & 1) * 8;
    const int bK   = tid >> 4;          // 0..15
    const int bN8  = (tid & 15) * 8;    // 0..120

    // ldmatrix lane-address components
    const int lmARowOff = (lane & 7) + ((lane >> 3) & 1) * 8;
    const int lmAColOff = (lane >> 4) * 8;
    const int lmBRow    = lane & 15;
    const int lmBColOff = (lane >> 4) * 8;

    const __half* Ap = A + (size_t)(by * 128 + aRow) * K + aK0;
    const __half* Bp = B + (size_t)bK * N + bx * 128 + bN8;

    float acc[4][4][4];
#pragma unroll
    for (int i = 0; i < 4; i++)
#pragma unroll
        for (int j = 0; j < 4; j++)
#pragma unroll
            for (int r = 0; r < 4; r++) acc[i][j][r] = 0.0f;

    // prefetch stage 0
    uint4 aV = *(const uint4*)Ap;   Ap += 16;
    uint4 bV = *(const uint4*)Bp;   Bp += (size_t)16 * N;

    *(uint4*)&As[0][aRow * AST + aK0] = aV;
    *(uint4*)&Bs[0][bK * BSN + bN8]   = bV;
    __syncthreads();

    const int nIter = K >> 4;
    for (int it = 0; it < nIter; it++) {
        const int buf = it & 1;
        const bool more = (it + 1 < nIter);

        if (more) {
            aV = *(const uint4*)Ap;   Ap += 16;
            bV = *(const uint4*)Bp;   Bp += (size_t)16 * N;
        }

        {
            const uint32_t asBase = (uint32_t)__cvta_generic_to_shared(&As[buf][0]);
            const uint32_t bsBase = (uint32_t)__cvta_generic_to_shared(&Bs[buf][0]);
            uint32_t af[4][4], bf[2][4];
#pragma unroll
            for (int mt = 0; mt < 4; mt++) {
                int arow = wm + mt * 16 + lmARowOff;
                ldmatrix_x4(af[mt], asBase + (arow * AST + lmAColOff) * 2);
            }
#pragma unroll
            for (int p = 0; p < 2; p++) {
                int col = wn + p * 16 + lmBColOff;
                ldmatrix_x4_trans(bf[p], bsBase + (lmBRow * BSN + col) * 2);
            }
#pragma unroll
            for (int mt = 0; mt < 4; mt++)
#pragma unroll
                for (int p = 0; p < 2; p++) {
                    mma_f16(acc[mt][2 * p],     af[mt], bf[p]);
                    mma_f16(acc[mt][2 * p + 1], af[mt], bf[p] + 2);
                }
        }

        if (more) {
            int nb = buf ^ 1;
            *(uint4*)&As[nb][aRow * AST + aK0] = aV;
            *(uint4*)&Bs[nb][bK * BSN + bN8]   = bV;
            __syncthreads();
        }
    }

    // epilogue
#pragma unroll
    for (int mt = 0; mt < 4; mt++) {
#pragma unroll
        for (int nt = 0; nt < 4; nt++) {
            int row0 = by * 128 + wm + mt * 16 + g;
            int col  = bx * 128 + wn + nt * 8 + 2 * tg;
            float bc0 = bias[col], bc1 = bias[col + 1];
            float v0 = acc[mt][nt][0] + bc0;
            float v1 = acc[mt][nt][1] + bc1;
            float v2 = acc[mt][nt][2] + bc0;
            float v3 = acc[mt][nt][3] + bc1;
            if (GELU) {
                v0 = 0.5f * v0 * (1.0f + erff(v0 * 0.70710678118654752f));
                v1 = 0.5f * v1 * (1.0f + erff(v1 * 0.70710678118654752f));
                v2 = 0.5f * v2 * (1.0f + erff(v2 * 0.70710678118654752f));
                v3 = 0.5f * v3 * (1.0f + erff(v3 * 0.70710678118654752f));
            }
            if (ROPE) {
                if (sel != 2) {   // Q and K only
                    int i  = (col & 63) >> 1;
                    int s0 = row0 & (SS - 1);
                    int s1 = (row0 + 8) & (SS - 1);
                    float c0 = ct[s0 * 32 + i], n0 = st[s0 * 32 + i];
                    float c1 = ct[s1 * 32 + i], n1 = st[s1 * 32 + i];
                    float t0 = v0 * c0 - v1 * n0;
                    v1 = v0 * n0 + v1 * c0;  v0 = t0;
                    float t2 = v2 * c1 - v3 * n1;
                    v3 = v2 * n1 + v3 * c1;  v2 = t2;
                }
            }
            if (OUTH == 1) {
                __half* Ch = (__half*)C;
                *(uint32_t*)(Ch + (size_t)row0 * N + col)       = pack_h2(v0, v1);
                *(uint32_t*)(Ch + (size_t)(row0 + 8) * N + col) = pack_h2(v2, v3);
            } else {
                float* Cf = (float*)C;
                *(float2*)(Cf + (size_t)row0 * N + col)       = make_float2(v0, v1);
                *(float2*)(Cf + (size_t)(row0 + 8) * N + col) = make_float2(v2, v3);
                if (OUTH == 2) {
                    *(uint32_t*)(Cdual + (size_t)row0 * N + col)       = pack_h2(v0, v1);
                    *(uint32_t*)(Cdual + (size_t)(row0 + 8) * N + col) = pack_h2(v2, v3);
                }
            }
        }
    }
}

// ---------------- naive head GEMM: out[M x 32] = h @ Wh + bh ----------------
__global__ void head_gemm_kernel(const float* __restrict__ h,
                                 const float* __restrict__ Wh,
                                 const float* __restrict__ bh,
                                 float* __restrict__ out) {
    int idx = blockIdx.x * blockDim.x + threadIdx.x;
    int n = idx & (PP - 1);
    int m = idx / PP;
    float acc = bh[n];
    const float* hp = h + (size_t)m * DD;
#pragma unroll 8
    for (int k = 0; k < DD; k++) acc += hp[k] * Wh[k * PP + n];
    out[idx] = acc;
}

// ---------------- residual add + LayerNorm (h fp32 + hh fp16) ---------------
__global__ void add_ln_kernel(float* __restrict__ h, const float* __restrict__ d,
                              const float* __restrict__ g, const float* __restrict__ b,
                              __half* __restrict__ hh) {
    int row = blockIdx.x;
    int t   = threadIdx.x;
    float4 hv = *(float4*)(h + (size_t)row * DD + t * 4);
    float4 dv = *(const float4*)(d + (size_t)row * DD + t * 4);
    float v0 = hv.x + dv.x, v1 = hv.y + dv.y, v2 = hv.z + dv.z, v3 = hv.w + dv.w;
    float s  = v0 + v1 + v2 + v3;
    float s2 = v0 * v0 + v1 * v1 + v2 * v2 + v3 * v3;
#pragma unroll
    for (int off = 16; off; off >>= 1) {
        s  += __shfl_xor_sync(0xFFFFFFFF, s,  off);
        s2 += __shfl_xor_sync(0xFFFFFFFF, s2, off);
    }
    __shared__ float sh[8];
    int w = t >> 5, lane = t & 31;
    if (lane == 0) { sh[w] = s; sh[4 + w] = s2; }
    __syncthreads();
    s  = sh[0] + sh[1] + sh[2] + sh[3];
    s2 = sh[4] + sh[5] + sh[6] + sh[7];
    float mean = s * (1.0f / DD);
    float var  = s2 * (1.0f / DD) - mean * mean;
    float inv  = rsqrtf(var + 1e-5f);
    float4 gv = *(const float4*)(g + t * 4);
    float4 bv = *(const float4*)(b + t * 4);
    float4 o;
    o.x = (v0 - mean) * inv * gv.x + bv.x;
    o.y = (v1 - mean) * inv * gv.y + bv.y;
    o.z = (v2 - mean) * inv * gv.z + bv.z;
    o.w = (v3 - mean) * inv * gv.w + bv.w;
    *(float4*)(h + (size_t)row * DD + t * 4) = o;
    uint32_t* hp2 = (uint32_t*)(hh + (size_t)row * DD + t * 4);
    hp2[0] = pack_h2(o.x, o.y);
    hp2[1] = pack_h2(o.z, o.w);
}

// ---------------- fp16 tensor-core flash attention ---------------------------
#define HST 72

__global__ void __launch_bounds__(128)
attn4_kernel(const __half* __restrict__ q, const __half* __restrict__ k,
             const __half* __restrict__ v, const int* __restrict__ vids,
             const float* __restrict__ mask,
             const float* __restrict__ u_same, const float* __restrict__ u_cross,
             __half* __restrict__ o) {
    __shared__ __half Qs[64 * HST];
    __shared__ __half Ks[64 * HST];
    __shared__ __half Vs[64 * HST];
    __shared__ __half Ps[64 * HST];
    __shared__ int   svid[64];
    __shared__ float smask[64];

    const int tid  = threadIdx.x;
    const int warp = tid >> 5;
    const int lane = tid & 31;
    const int g    = lane >> 2;
    const int tg   = lane & 3;
    const int qw   = warp * 16;

    const int lmARowOff = (lane & 7) + ((lane >> 3) & 1) * 8;
    const int lmAColOff = (lane >> 4) * 8;
    const int lmBRowOff = (lane & 7) + ((lane >> 4) & 1) * 8;
    const int lmBColOff = ((lane >> 3) & 1) * 8;
    const int lmVRow    = lane & 15;
    const int lmVColOff = (lane >> 4) * 8;

    int qt = blockIdx.x & (SS / 64 - 1);
    int bh = blockIdx.x / (SS / 64);
    int hh = bh & (HH - 1);
    int b  = bh / HH;
    int q0 = qt * 64;

    const float us = u_same[hh], uc = u_cross[hh];

    const uint32_t qsBase = (uint32_t)__cvta_generic_to_shared(Qs);
    const uint32_t ksBase = (uint32_t)__cvta_generic_to_shared(Ks);
    const uint32_t vsBase = (uint32_t)__cvta_generic_to_shared(Vs);
    const uint32_t psBase = (uint32_t)__cvta_generic_to_shared(Ps);

    {
        const __half* qbase = q + ((size_t)(b * SS + q0)) * DD + hh * HD;
#pragma unroll
        for (int r = 0; r < 4; r++) {
            int idx = tid + r * 128;
            int qi  = idx >> 3;
            int c8  = (idx & 7) * 8;
            *(uint4*)&Qs[qi * HST + c8] = *(const uint4*)(qbase + (size_t)qi * DD + c8);
        }
    }

    int vq0 = vids[b * SS + q0 + qw + g];
    int vq1 = vids[b * SS + q0 + qw + g + 8];
    float m0 = -1e30f, m1 = -1e30f, l0 = 0.0f, l1 = 0.0f;
    float oacc[8][4];
#pragma unroll
    for (int nt = 0; nt < 8; nt++)
#pragma unroll
        for (int r = 0; r < 4; r++) oacc[nt][r] = 0.0f;
    __syncthreads();

    for (int kt = 0; kt < SS; kt += 64) {
        const __half* kbase = k + ((size_t)(b * SS + kt)) * DD + hh * HD;
        const __half* vbase = v + ((size_t)(b * SS + kt)) * DD + hh * HD;
#pragma unroll
        for (int r = 0; r < 4; r++) {
            int idx = tid + r * 128;
            int ki  = idx >> 3;
            int c8  = (idx & 7) * 8;
            *(uint4*)&Ks[ki * HST + c8] = *(const uint4*)(kbase + (size_t)ki * DD + c8);
            *(uint4*)&Vs[ki * HST + c8] = *(const uint4*)(vbase + (size_t)ki * DD + c8);
        }
        if (tid < 64) {
            svid[tid]  = vids[b * SS + kt + tid];
            smask[tid] = (1.0f - mask[b * SS + kt + tid]) * -1e9f;
        }
        __syncthreads();

        float s[8][4];
#pragma unroll
        for (int nt = 0; nt < 8; nt++)
#pragma unroll
            for (int r = 0; r < 4; r++) s[nt][r] = 0.0f;
#pragma unroll
        for (int ks = 0; ks < 64; ks += 16) {
            uint32_t av[4];
            ldmatrix_x4(av, qsBase + ((qw + lmARowOff) * HST + ks + lmAColOff) * 2);
#pragma unroll
            for (int p = 0; p < 4; p++) {
                uint32_t r[4];
                int n = p * 16 + lmBRowOff;
                ldmatrix_x4(r, ksBase + (n * HST + ks + lmBColOff) * 2);
                mma_f16(s[2 * p],     av, r);
                mma_f16(s[2 * p + 1], av, r + 2);
            }
        }

        float rmax0 = -1e30f, rmax1 = -1e30f;
#pragma unroll
        for (int nt = 0; nt < 8; nt++) {
            int c0 = nt * 8 + 2 * tg;
            int c1 = c0 + 1;
            float bia0 = smask[c0], bia1 = smask[c1];
            s[nt][0] = s[nt][0] * 0.125f + (svid[c0] == vq0 ? us : uc) + bia0;
            s[nt][1] = s[nt][1] * 0.125f + (svid[c1] == vq0 ? us : uc) + bia1;
            s[nt][2] = s[nt][2] * 0.125f + (svid[c0] == vq1 ? us : uc) + bia0;
            s[nt][3] = s[nt][3] * 0.125f + (svid[c1] == vq1 ? us : uc) + bia1;
            rmax0 = fmaxf(rmax0, fmaxf(s[nt][0], s[nt][1]));
            rmax1 = fmaxf(rmax1, fmaxf(s[nt][2], s[nt][3]));
        }
        rmax0 = fmaxf(rmax0, __shfl_xor_sync(0xFFFFFFFF, rmax0, 1));
        rmax0 = fmaxf(rmax0, __shfl_xor_sync(0xFFFFFFFF, rmax0, 2));
        rmax1 = fmaxf(rmax1, __shfl_xor_sync(0xFFFFFFFF, rmax1, 1));
        rmax1 = fmaxf(rmax1, __shfl_xor_sync(0xFFFFFFFF, rmax1, 2));
        float newm0 = fmaxf(m0, rmax0);
        float newm1 = fmaxf(m1, rmax1);
        float corr0 = __expf(m0 - newm0);
        float corr1 = __expf(m1 - newm1);
        m0 = newm0; m1 = newm1;

        float rsum0 = 0.0f, rsum1 = 0.0f;
#pragma unroll
        for (int nt = 0; nt < 8; nt++) {
            float p0 = __expf(s[nt][0] - m0);
            float p1 = __expf(s[nt][1] - m0);
            float p2 = __expf(s[nt][2] - m1);
            float p3 = __expf(s[nt][3] - m1);
            rsum0 += p0 + p1;
            rsum1 += p2 + p3;
            int c0 = nt * 8 + 2 * tg;
            *(uint32_t*)&Ps[(qw + g)     * HST + c0] = pack_h2(p0, p1);
            *(uint32_t*)&Ps[(qw + g + 8) * HST + c0] = pack_h2(p2, p3);
            oacc[nt][0] *= corr0;
            oacc[nt][1] *= corr0;
            oacc[nt][2] *= corr1;
            oacc[nt][3] *= corr1;
        }
        rsum0 += __shfl_xor_sync(0xFFFFFFFF, rsum0, 1);
        rsum0 += __shfl_xor_sync(0xFFFFFFFF, rsum0, 2);
        rsum1 += __shfl_xor_sync(0xFFFFFFFF, rsum1, 1);
        rsum1 += __shfl_xor_sync(0xFFFFFFFF, rsum1, 2);
        l0 = l0 * corr0 + rsum0;
        l1 = l1 * corr1 + rsum1;
        __syncwarp();

#pragma unroll
        for (int ks = 0; ks < 64; ks += 16) {
            uint32_t av[4];
            ldmatrix_x4(av, psBase + ((qw + lmARowOff) * HST + ks + lmAColOff) * 2);
#pragma unroll
            for (int p = 0; p < 4; p++) {
                uint32_t r[4];
                int col = p * 16 + lmVColOff;
                ldmatrix_x4_trans(r, vsBase + ((ks + lmVRow) * HST + col) * 2);
                mma_f16(oacc[2 * p],     av, r);
                mma_f16(oacc[2 * p + 1], av, r + 2);
            }
        }
        __syncthreads();
    }

    float invl0 = 1.0f / l0;
    float invl1 = 1.0f / l1;
    __half* ob0 = o + ((size_t)(b * SS + q0 + qw + g)) * DD + hh * HD;
    __half* ob1 = ob0 + (size_t)8 * DD;
#pragma unroll
    for (int nt = 0; nt < 8; nt++) {
        int c = nt * 8 + 2 * tg;
        *(uint32_t*)(ob0 + c) = pack_h2(oacc[nt][0] * invl0, oacc[nt][1] * invl0);
        *(uint32_t*)(ob1 + c) = pack_h2(oacc[nt][2] * invl1, oacc[nt][3] * invl1);
    }
}

// ---------------- driver -----------------------------------------------------
extern "C" void kernel_launch(void* const* d_in, const int* in_sizes, int n_in,
                              void* d_out, int out_size) {
    const float* x      = (const float*)d_in[0];
    const int*   vids   = (const int*)  d_in[1];
    const float* mask   = (const float*)d_in[2];
    const float* W_pe   = (const float*)d_in[3];
    const float* b_pe   = (const float*)d_in[4];
    const float* Wq     = (const float*)d_in[5];
    const float* bq     = (const float*)d_in[6];
    const float* Wk     = (const float*)d_in[7];
    const float* bk     = (const float*)d_in[8];
    const float* Wv     = (const float*)d_in[9];
    const float* bv     = (const float*)d_in[10];
    const float* Wo     = (const float*)d_in[11];
    const float* bo     = (const float*)d_in[12];
    const float* u_same = (const float*)d_in[13];
    const float* u_cross= (const float*)d_in[14];
    const float* g1     = (const float*)d_in[15];
    const float* be1    = (const float*)d_in[16];
    const float* W1     = (const float*)d_in[17];
    const float* b1f    = (const float*)d_in[18];
    const float* W2     = (const float*)d_in[19];
    const float* b2f    = (const float*)d_in[20];
    const float* g2     = (const float*)d_in[21];
    const float* be2    = (const float*)d_in[22];
    const float* Wh     = (const float*)d_in[23];
    const float* bh     = (const float*)d_in[24];
    float* out = (float*)d_out;

    float *ph, *pt, *pc, *ps;
    __half *phh, *pq, *pk, *pv, *po, *pff, *pxh, *pwh;
    cudaGetSymbolAddress((void**)&ph,  g_h);
    cudaGetSymbolAddress((void**)&pt,  g_t);
    cudaGetSymbolAddress((void**)&phh, g_hh);
    cudaGetSymbolAddress((void**)&pq,  g_qh);
    cudaGetSymbolAddress((void**)&pk,  g_kh);
    cudaGetSymbolAddress((void**)&pv,  g_vh);
    cudaGetSymbolAddress((void**)&po,  g_oh);
    cudaGetSymbolAddress((void**)&pff, g_ffh);
    cudaGetSymbolAddress((void**)&pxh, g_xh);
    cudaGetSymbolAddress((void**)&pwh, g_wh);
    cudaGetSymbolAddress((void**)&pc,  g_cos);
    cudaGetSymbolAddress((void**)&ps,  g_sin);

    convert_kernel<<<(NX + TOTAL_W + 255) / 256, 256>>>(
        x, W_pe, Wq, Wk, Wv, Wo, W1, W2, pxh, pwh);
    rope_tables_kernel<<<(SS * 32 + 255) / 256, 256>>>(pc, ps);

    const __half* wpe = pwh + OFF_WPE;
    // pe: h (fp32) + hh (fp16) = x @ W_pe + b_pe
    tgemm_bias<0, 0, 2><<<dim3(DD / 128, MM / 128), 256>>>(
        pxh, wpe, wpe, wpe, b_pe, b_pe, b_pe, ph, ph, ph, phh,
        pc, ps, MM, DD, PP, DD / 128);

    for (int l = 0; l < LL; l++) {
        const __half* Wql = pwh + OFF_WQ + (size_t)l * S_W;
        const __half* Wkl = pwh + OFF_WK + (size_t)l * S_W;
        const __half* Wvl = pwh + OFF_WV + (size_t)l * S_W;
        const __half* Wol = pwh + OFF_WO + (size_t)l * S_W;
        const __half* W1l = pwh + OFF_W1 + (size_t)l * S_W1;
        const __half* W2l = pwh + OFF_W2 + (size_t)l * S_W1;

        // fused Q,K,V projection with inline RoPE on Q,K
        tgemm_bias<0, 1, 1><<<dim3(3 * (DD / 128), MM / 128), 256>>>(
            phh, Wql, Wkl, Wvl, bq + l * DD, bk + l * DD, bv + l * DD,
            pq, pk, pv, (__half*)0, pc, ps, MM, DD, DD, DD / 128);

        attn4_kernel<<<BB * HH * (SS / 64), 128>>>(
            pq, pk, pv, vids, mask, u_same + l * HH, u_cross + l * HH, po);

        tgemm_bias<0, 0, 0><<<dim3(DD / 128, MM / 128), 256>>>(
            po, Wol, Wol, Wol, bo + l * DD, bo + l * DD, bo + l * DD,
            pt, pt, pt, (__half*)0, pc, ps, MM, DD, DD, DD / 128);
        add_ln_kernel<<<MM, 128>>>(ph, pt, g1 + l * DD, be1 + l * DD, phh);

        tgemm_bias<1, 0, 1><<<dim3(DF / 128, MM / 128), 256>>>(
            phh, W1l, W1l, W1l, b1f + l * DF, b1f + l * DF, b1f + l * DF,
            pff, pff, pff, (__half*)0, pc, ps, MM, DF, DD, DF / 128);
        tgemm_bias<0, 0, 0><<<dim3(DD / 128, MM / 128), 256>>>(
            pff, W2l, W2l, W2l, b2f + l * DD, b2f + l * DD, b2f + l * DD,
            pt, pt, pt, (__half*)0, pc, ps, MM, DD, DF, DD / 128);
        add_ln_kernel<<<MM, 128>>>(ph, pt, g2 + l * DD, be2 + l * DD, phh);
    }

    head_gemm_kernel<<<(MM * PP) / 256, 256>>>(ph, Wh, bh, out);
}

// round 13
// speedup vs baseline: 2.1343x; 1.1619x over previous
#include <cuda_runtime.h>
#include <cuda_fp16.h>
#include <math.h>
#include <stdint.h>

#define BB  4
#define SS  2048
#define PP  32
#define DD  512
#define HH  8
#define LL  2
#define DF  2048
#define HD  64
#define MM  (BB*SS)   /* 8192 rows */

#define S_W   (DD*DD)
#define S_W1  (DD*DF)
#define OFF_WPE 0
#define OFF_WQ  (PP*DD)
#define OFF_WK  (OFF_WQ + LL*S_W)
#define OFF_WV  (OFF_WK + LL*S_W)
#define OFF_WO  (OFF_WV + LL*S_W)
#define OFF_W1  (OFF_WO + LL*S_W)
#define OFF_W2  (OFF_W1 + LL*S_W1)
#define TOTAL_W (OFF_W2 + LL*S_W1)
#define NX      (MM*PP)

// ---------------- scratch (device globals; no allocations allowed) ----------
__device__ float  g_h [MM*DD];
__device__ float  g_t [MM*DD];
__device__ __half g_hh [MM*DD];
__device__ __half g_qh [MM*DD];
__device__ __half g_kh [MM*DD];
__device__ __half g_vh [MM*DD];
__device__ __half g_oh [MM*DD];
__device__ __half g_ffh[MM*DF];
__device__ __half g_xh [NX];
__device__ __half g_wh [TOTAL_W];
__device__ float  g_cos[SS*32];
__device__ float  g_sin[SS*32];

// ---------------- helpers ----------------------------------------------------
__device__ __forceinline__ void mma_f16(float* c, const uint32_t* a, const uint32_t* b) {
    asm volatile(
        "mma.sync.aligned.m16n8k16.row.col.f32.f16.f16.f32 "
        "{%0,%1,%2,%3}, {%4,%5,%6,%7}, {%8,%9}, {%0,%1,%2,%3};\n"
        : "+f"(c[0]), "+f"(c[1]), "+f"(c[2]), "+f"(c[3])
        : "r"(a[0]), "r"(a[1]), "r"(a[2]), "r"(a[3]), "r"(b[0]), "r"(b[1]));
}

__device__ __forceinline__ uint32_t pack_h2(float lo, float hi) {
    __half2 h = __floats2half2_rn(lo, hi);
    return *(uint32_t*)&h;
}

__device__ __forceinline__ void ldmatrix_x4(uint32_t* r, uint32_t saddr) {
    asm volatile("ldmatrix.sync.aligned.m8n8.x4.shared.b16 {%0,%1,%2,%3}, [%4];"
                 : "=r"(r[0]), "=r"(r[1]), "=r"(r[2]), "=r"(r[3]) : "r"(saddr));
}
__device__ __forceinline__ void ldmatrix_x4_trans(uint32_t* r, uint32_t saddr) {
    asm volatile("ldmatrix.sync.aligned.m8n8.x4.trans.shared.b16 {%0,%1,%2,%3}, [%4];"
                 : "=r"(r[0]), "=r"(r[1]), "=r"(r[2]), "=r"(r[3]) : "r"(saddr));
}

__device__ __forceinline__ void cp_async16(uint32_t saddr, const void* g) {
    asm volatile("cp.async.cg.shared.global [%0], [%1], 16;" :: "r"(saddr), "l"(g));
}
__device__ __forceinline__ void cp_async4(uint32_t saddr, const void* g) {
    asm volatile("cp.async.ca.shared.global [%0], [%1], 4;" :: "r"(saddr), "l"(g));
}
__device__ __forceinline__ void cp_commit() {
    asm volatile("cp.async.commit_group;" ::: "memory");
}
template <int N>
__device__ __forceinline__ void cp_wait() {
    asm volatile("cp.async.wait_group %0;" :: "n"(N) : "memory");
}

// ---------------- fp32 -> fp16 conversion of x + all weights ----------------
__global__ void convert_kernel(const float* __restrict__ x,
                               const float* __restrict__ wpe,
                               const float* __restrict__ wq, const float* __restrict__ wk,
                               const float* __restrict__ wv, const float* __restrict__ wo,
                               const float* __restrict__ w1, const float* __restrict__ w2,
                               __half* __restrict__ xh, __half* __restrict__ wh) {
    int idx = blockIdx.x * blockDim.x + threadIdx.x;
    if (idx < NX) { xh[idx] = __float2half(x[idx]); return; }
    int j = idx - NX;
    if (j >= TOTAL_W) return;
    const float* src;
    int off;
    if      (j < OFF_WQ) { src = wpe; off = OFF_WPE; }
    else if (j < OFF_WK) { src = wq;  off = OFF_WQ; }
    else if (j < OFF_WV) { src = wk;  off = OFF_WK; }
    else if (j < OFF_WO) { src = wv;  off = OFF_WV; }
    else if (j < OFF_W1) { src = wo;  off = OFF_WO; }
    else if (j < OFF_W2) { src = w1;  off = OFF_W1; }
    else                 { src = w2;  off = OFF_W2; }
    wh[j] = __float2half(src[j - off]);
}

// ---------------- RoPE tables ------------------------------------------------
__global__ void rope_tables_kernel(float* __restrict__ ct, float* __restrict__ st) {
    int idx = blockIdx.x * blockDim.x + threadIdx.x;
    if (idx >= SS * 32) return;
    int pos = idx >> 5;
    int i   = idx & 31;
    int fidx = (2 * i) & 31;
    float ex  = (float)(2 * fidx) / 64.0f;
    float inv = 1.0f / powf(10000.0f, ex);
    float ang = (float)pos * inv;
    ct[idx] = cosf(ang);
    st[idx] = sinf(ang);
}

// ---------------- FP16 tensor-core GEMM, 4-stage cp.async pipeline -----------
// C = A[MxK](half) @ Bsel[KxN](half) + bias_sel.
// OUTH: 0=float out, 1=half out, 2=float C + half Cdual. ROPE on sel 0,1.
#define AST 24
#define BSN 136
#define STG 4

template <int GELU, int ROPE, int OUTH>
__global__ void __launch_bounds__(256)
tgemm_bias(const __half* __restrict__ A,
           const __half* __restrict__ B0, const __half* __restrict__ B1,
           const __half* __restrict__ B2,
           const float* __restrict__ bias0, const float* __restrict__ bias1,
           const float* __restrict__ bias2,
           void* __restrict__ C0, void* __restrict__ C1, void* __restrict__ C2,
           __half* __restrict__ Cdual,
           const float* __restrict__ ct, const float* __restrict__ st,
           int M, int N, int K, int ntile) {
    __shared__ __half As[STG][128 * AST];
    __shared__ __half Bs[STG][16 * BSN];

    const int sel = blockIdx.x / ntile;
    const int bx  = blockIdx.x - sel * ntile;
    const int by  = blockIdx.y;
    const __half* B    = (sel == 0) ? B0 : (sel == 1) ? B1 : B2;
    const float*  bias = (sel == 0) ? bias0 : (sel == 1) ? bias1 : bias2;
    void*         C    = (sel == 0) ? C0 : (sel == 1) ? C1 : C2;

    const int tid  = threadIdx.x;
    const int warp = tid >> 5;
    const int lane = tid & 31;
    const int g    = lane >> 2;
    const int tg   = lane & 3;
    const int wm   = (warp & 1) * 64;
    const int wn   = (warp >> 1) * 32;

    const int aRow = tid >> 1;
    const int aK0  = (tid & 1) * 8;
    const int bK   = tid >> 4;
    const int bN8  = (tid & 15) * 8;

    const int lmARowOff = (lane & 7) + ((lane >> 3) & 1) * 8;
    const int lmAColOff = (lane >> 4) * 8;
    const int lmBRow    = lane & 15;
    const int lmBColOff = (lane >> 4) * 8;

    const __half* Ap = A + (size_t)(by * 128 + aRow) * K + aK0;
    const __half* Bp = B + (size_t)bK * N + bx * 128 + bN8;

    uint32_t aDst[STG], bDst[STG];
#pragma unroll
    for (int s = 0; s < STG; s++) {
        aDst[s] = (uint32_t)__cvta_generic_to_shared(&As[s][aRow * AST + aK0]);
        bDst[s] = (uint32_t)__cvta_generic_to_shared(&Bs[s][bK * BSN + bN8]);
    }

    float acc[4][4][4];
#pragma unroll
    for (int i = 0; i < 4; i++)
#pragma unroll
        for (int j = 0; j < 4; j++)
#pragma unroll
            for (int r = 0; r < 4; r++) acc[i][j][r] = 0.0f;

    const int nIter = K >> 4;

    // prologue: issue stages 0..STG-2
#pragma unroll
    for (int s = 0; s < STG - 1; s++) {
        if (s < nIter) {
            cp_async16(aDst[s], Ap + s * 16);
            cp_async16(bDst[s], Bp + (size_t)(s * 16) * N);
        }
        cp_commit();
    }

    for (int it = 0; it < nIter; it++) {
        cp_wait<STG - 2>();
        __syncthreads();

        const int buf = it & (STG - 1);
        {
            const uint32_t asBase = (uint32_t)__cvta_generic_to_shared(&As[buf][0]);
            const uint32_t bsBase = (uint32_t)__cvta_generic_to_shared(&Bs[buf][0]);
            uint32_t af[4][4], bf[2][4];
#pragma unroll
            for (int mt = 0; mt < 4; mt++) {
                int arow = wm + mt * 16 + lmARowOff;
                ldmatrix_x4(af[mt], asBase + (arow * AST + lmAColOff) * 2);
            }
#pragma unroll
            for (int p = 0; p < 2; p++) {
                int col = wn + p * 16 + lmBColOff;
                ldmatrix_x4_trans(bf[p], bsBase + (lmBRow * BSN + col) * 2);
            }
#pragma unroll
            for (int mt = 0; mt < 4; mt++)
#pragma unroll
                for (int p = 0; p < 2; p++) {
                    mma_f16(acc[mt][2 * p],     af[mt], bf[p]);
                    mma_f16(acc[mt][2 * p + 1], af[mt], bf[p] + 2);
                }
        }

        const int nxt = it + STG - 1;
        if (nxt < nIter) {
            cp_async16(aDst[nxt & (STG - 1)], Ap + nxt * 16);
            cp_async16(bDst[nxt & (STG - 1)], Bp + (size_t)(nxt * 16) * N);
        }
        cp_commit();
    }

    // epilogue
#pragma unroll
    for (int mt = 0; mt < 4; mt++) {
#pragma unroll
        for (int nt = 0; nt < 4; nt++) {
            int row0 = by * 128 + wm + mt * 16 + g;
            int col  = bx * 128 + wn + nt * 8 + 2 * tg;
            float bc0 = bias[col], bc1 = bias[col + 1];
            float v0 = acc[mt][nt][0] + bc0;
            float v1 = acc[mt][nt][1] + bc1;
            float v2 = acc[mt][nt][2] + bc0;
            float v3 = acc[mt][nt][3] + bc1;
            if (GELU) {
                v0 = 0.5f * v0 * (1.0f + erff(v0 * 0.70710678118654752f));
                v1 = 0.5f * v1 * (1.0f + erff(v1 * 0.70710678118654752f));
                v2 = 0.5f * v2 * (1.0f + erff(v2 * 0.70710678118654752f));
                v3 = 0.5f * v3 * (1.0f + erff(v3 * 0.70710678118654752f));
            }
            if (ROPE) {
                if (sel != 2) {
                    int i  = (col & 63) >> 1;
                    int s0 = row0 & (SS - 1);
                    int s1 = (row0 + 8) & (SS - 1);
                    float c0 = ct[s0 * 32 + i], n0 = st[s0 * 32 + i];
                    float c1 = ct[s1 * 32 + i], n1 = st[s1 * 32 + i];
                    float t0 = v0 * c0 - v1 * n0;
                    v1 = v0 * n0 + v1 * c0;  v0 = t0;
                    float t2 = v2 * c1 - v3 * n1;
                    v3 = v2 * n1 + v3 * c1;  v2 = t2;
                }
            }
            if (OUTH == 1) {
                __half* Ch = (__half*)C;
                *(uint32_t*)(Ch + (size_t)row0 * N + col)       = pack_h2(v0, v1);
                *(uint32_t*)(Ch + (size_t)(row0 + 8) * N + col) = pack_h2(v2, v3);
            } else {
                float* Cf = (float*)C;
                *(float2*)(Cf + (size_t)row0 * N + col)       = make_float2(v0, v1);
                *(float2*)(Cf + (size_t)(row0 + 8) * N + col) = make_float2(v2, v3);
                if (OUTH == 2) {
                    *(uint32_t*)(Cdual + (size_t)row0 * N + col)       = pack_h2(v0, v1);
                    *(uint32_t*)(Cdual + (size_t)(row0 + 8) * N + col) = pack_h2(v2, v3);
                }
            }
        }
    }
}

// ---------------- naive head GEMM --------------------------------------------
__global__ void head_gemm_kernel(const float* __restrict__ h,
                                 const float* __restrict__ Wh,
                                 const float* __restrict__ bh,
                                 float* __restrict__ out) {
    int idx = blockIdx.x * blockDim.x + threadIdx.x;
    int n = idx & (PP - 1);
    int m = idx / PP;
    float acc = bh[n];
    const float* hp = h + (size_t)m * DD;
#pragma unroll 8
    for (int k = 0; k < DD; k++) acc += hp[k] * Wh[k * PP + n];
    out[idx] = acc;
}

// ---------------- residual add + LayerNorm (h fp32 + hh fp16) ----------------
__global__ void add_ln_kernel(float* __restrict__ h, const float* __restrict__ d,
                              const float* __restrict__ g, const float* __restrict__ b,
                              __half* __restrict__ hh) {
    int row = blockIdx.x;
    int t   = threadIdx.x;
    float4 hv = *(float4*)(h + (size_t)row * DD + t * 4);
    float4 dv = *(const float4*)(d + (size_t)row * DD + t * 4);
    float v0 = hv.x + dv.x, v1 = hv.y + dv.y, v2 = hv.z + dv.z, v3 = hv.w + dv.w;
    float s  = v0 + v1 + v2 + v3;
    float s2 = v0 * v0 + v1 * v1 + v2 * v2 + v3 * v3;
#pragma unroll
    for (int off = 16; off; off >>= 1) {
        s  += __shfl_xor_sync(0xFFFFFFFF, s,  off);
        s2 += __shfl_xor_sync(0xFFFFFFFF, s2, off);
    }
    __shared__ float sh[8];
    int w = t >> 5, lane = t & 31;
    if (lane == 0) { sh[w] = s; sh[4 + w] = s2; }
    __syncthreads();
    s  = sh[0] + sh[1] + sh[2] + sh[3];
    s2 = sh[4] + sh[5] + sh[6] + sh[7];
    float mean = s * (1.0f / DD);
    float var  = s2 * (1.0f / DD) - mean * mean;
    float inv  = rsqrtf(var + 1e-5f);
    float4 gv = *(const float4*)(g + t * 4);
    float4 bv = *(const float4*)(b + t * 4);
    float4 o;
    o.x = (v0 - mean) * inv * gv.x + bv.x;
    o.y = (v1 - mean) * inv * gv.y + bv.y;
    o.z = (v2 - mean) * inv * gv.z + bv.z;
    o.w = (v3 - mean) * inv * gv.w + bv.w;
    *(float4*)(h + (size_t)row * DD + t * 4) = o;
    uint32_t* hp2 = (uint32_t*)(hh + (size_t)row * DD + t * 4);
    hp2[0] = pack_h2(o.x, o.y);
    hp2[1] = pack_h2(o.z, o.w);
}

// ---------------- fp16 flash attention, 2-stage cp.async K/V -----------------
// Dynamic smem layout (halfs unless noted):
//   Qs      [64*72]          @ 0
//   Ks[2]   [64*72] each     @ 4608, 9216
//   Vs[2]   [64*72] each     @ 13824, 18432
//   Ps      [64*72]          @ 23040
//   svid[2] int[64]          @ 27648h (= byte 55296)
//   smraw[2] float[64]       after svid
#define HST 72
#define ATTN_DSMEM (27648 * 2 + 2 * 64 * 4 + 2 * 64 * 4)

__global__ void __launch_bounds__(128)
attn4_kernel(const __half* __restrict__ q, const __half* __restrict__ k,
             const __half* __restrict__ v, const int* __restrict__ vids,
             const float* __restrict__ mask,
             const float* __restrict__ u_same, const float* __restrict__ u_cross,
             __half* __restrict__ o) {
    extern __shared__ char dsm[];
    __half* Qs  = (__half*)dsm;
    __half* Ks0 = Qs  + 64 * HST;
    __half* Ks1 = Ks0 + 64 * HST;
    __half* Vs0 = Ks1 + 64 * HST;
    __half* Vs1 = Vs0 + 64 * HST;
    __half* Ps  = Vs1 + 64 * HST;
    int*    svid0 = (int*)(Ps + 64 * HST);
    int*    svid1 = svid0 + 64;
    float*  smraw0 = (float*)(svid1 + 64);
    float*  smraw1 = smraw0 + 64;

    const int tid  = threadIdx.x;
    const int warp = tid >> 5;
    const int lane = tid & 31;
    const int g    = lane >> 2;
    const int tg   = lane & 3;
    const int qw   = warp * 16;

    const int lmARowOff = (lane & 7) + ((lane >> 3) & 1) * 8;
    const int lmAColOff = (lane >> 4) * 8;
    const int lmBRowOff = (lane & 7) + ((lane >> 4) & 1) * 8;
    const int lmBColOff = ((lane >> 3) & 1) * 8;
    const int lmVRow    = lane & 15;
    const int lmVColOff = (lane >> 4) * 8;

    int qt = blockIdx.x & (SS / 64 - 1);
    int bh = blockIdx.x / (SS / 64);
    int hh = bh & (HH - 1);
    int b  = bh / HH;
    int q0 = qt * 64;

    const float us = u_same[hh], uc = u_cross[hh];

    const uint32_t qsBase = (uint32_t)__cvta_generic_to_shared(Qs);
    const uint32_t psBase = (uint32_t)__cvta_generic_to_shared(Ps);
    const __half* kroot = k + ((size_t)(b * SS)) * DD + hh * HD;
    const __half* vroot = v + ((size_t)(b * SS)) * DD + hh * HD;

    const int stRow = tid >> 3;
    const int stC8  = (tid & 7) * 8;

    auto issue = [&](int it, int buf) {
        __half* Kb = buf ? Ks1 : Ks0;
        __half* Vb = buf ? Vs1 : Vs0;
        int*   sv  = buf ? svid1 : svid0;
        float* smr = buf ? smraw1 : smraw0;
        const __half* kb = kroot + (size_t)(it * 64) * DD;
        const __half* vb = vroot + (size_t)(it * 64) * DD;
#pragma unroll
        for (int r = 0; r < 4; r++) {
            int row = stRow + r * 16;
            cp_async16((uint32_t)__cvta_generic_to_shared(&Kb[row * HST + stC8]),
                       kb + (size_t)row * DD + stC8);
            cp_async16((uint32_t)__cvta_generic_to_shared(&Vb[row * HST + stC8]),
                       vb + (size_t)row * DD + stC8);
        }
        if (tid < 64) {
            cp_async4((uint32_t)__cvta_generic_to_shared(&sv[tid]),
                      vids + b * SS + it * 64 + tid);
            cp_async4((uint32_t)__cvta_generic_to_shared(&smr[tid]),
                      mask + b * SS + it * 64 + tid);
        }
    };

    // ---- stage Q (regular loads) ----
    {
        const __half* qbase = q + ((size_t)(b * SS + q0)) * DD + hh * HD;
#pragma unroll
        for (int r = 0; r < 4; r++) {
            int idx = tid + r * 128;
            int qi  = idx >> 3;
            int c8  = (idx & 7) * 8;
            *(uint4*)&Qs[qi * HST + c8] = *(const uint4*)(qbase + (size_t)qi * DD + c8);
        }
    }

    int vq0 = vids[b * SS + q0 + qw + g];
    int vq1 = vids[b * SS + q0 + qw + g + 8];
    float m0 = -1e30f, m1 = -1e30f, l0 = 0.0f, l1 = 0.0f;
    float oacc[8][4];
#pragma unroll
    for (int nt = 0; nt < 8; nt++)
#pragma unroll
        for (int r = 0; r < 4; r++) oacc[nt][r] = 0.0f;

    issue(0, 0);
    cp_commit();
    __syncthreads();   // Qs visible

    const int nTiles = SS / 64;
    for (int it = 0; it < nTiles; it++) {
        const int buf = it & 1;
        if (it + 1 < nTiles) issue(it + 1, buf ^ 1);
        cp_commit();
        cp_wait<1>();
        __syncthreads();

        const uint32_t ksBase = (uint32_t)__cvta_generic_to_shared(buf ? Ks1 : Ks0);
        const uint32_t vsBase = (uint32_t)__cvta_generic_to_shared(buf ? Vs1 : Vs0);
        const int*   sv  = buf ? svid1 : svid0;
        const float* smr = buf ? smraw1 : smraw0;

        // ---- S = Q @ K^T ----
        float s[8][4];
#pragma unroll
        for (int nt = 0; nt < 8; nt++)
#pragma unroll
            for (int r = 0; r < 4; r++) s[nt][r] = 0.0f;
#pragma unroll
        for (int ks = 0; ks < 64; ks += 16) {
            uint32_t av[4];
            ldmatrix_x4(av, qsBase + ((qw + lmARowOff) * HST + ks + lmAColOff) * 2);
#pragma unroll
            for (int p = 0; p < 4; p++) {
                uint32_t r[4];
                int n = p * 16 + lmBRowOff;
                ldmatrix_x4(r, ksBase + (n * HST + ks + lmBColOff) * 2);
                mma_f16(s[2 * p],     av, r);
                mma_f16(s[2 * p + 1], av, r + 2);
            }
        }

        // ---- bias + online softmax ----
        float rmax0 = -1e30f, rmax1 = -1e30f;
#pragma unroll
        for (int nt = 0; nt < 8; nt++) {
            int c0 = nt * 8 + 2 * tg;
            int c1 = c0 + 1;
            float bia0 = (1.0f - smr[c0]) * -1e9f;
            float bia1 = (1.0f - smr[c1]) * -1e9f;
            int   sv0 = sv[c0], sv1 = sv[c1];
            s[nt][0] = s[nt][0] * 0.125f + (sv0 == vq0 ? us : uc) + bia0;
            s[nt][1] = s[nt][1] * 0.125f + (sv1 == vq0 ? us : uc) + bia1;
            s[nt][2] = s[nt][2] * 0.125f + (sv0 == vq1 ? us : uc) + bia0;
            s[nt][3] = s[nt][3] * 0.125f + (sv1 == vq1 ? us : uc) + bia1;
            rmax0 = fmaxf(rmax0, fmaxf(s[nt][0], s[nt][1]));
            rmax1 = fmaxf(rmax1, fmaxf(s[nt][2], s[nt][3]));
        }
        rmax0 = fmaxf(rmax0, __shfl_xor_sync(0xFFFFFFFF, rmax0, 1));
        rmax0 = fmaxf(rmax0, __shfl_xor_sync(0xFFFFFFFF, rmax0, 2));
        rmax1 = fmaxf(rmax1, __shfl_xor_sync(0xFFFFFFFF, rmax1, 1));
        rmax1 = fmaxf(rmax1, __shfl_xor_sync(0xFFFFFFFF, rmax1, 2));
        float newm0 = fmaxf(m0, rmax0);
        float newm1 = fmaxf(m1, rmax1);
        float corr0 = __expf(m0 - newm0);
        float corr1 = __expf(m1 - newm1);
        m0 = newm0; m1 = newm1;

        float rsum0 = 0.0f, rsum1 = 0.0f;
#pragma unroll
        for (int nt = 0; nt < 8; nt++) {
            float p0 = __expf(s[nt][0] - m0);
            float p1 = __expf(s[nt][1] - m0);
            float p2 = __expf(s[nt][2] - m1);
            float p3 = __expf(s[nt][3] - m1);
            rsum0 += p0 + p1;
            rsum1 += p2 + p3;
            int c0 = nt * 8 + 2 * tg;
            *(uint32_t*)&Ps[(qw + g)     * HST + c0] = pack_h2(p0, p1);
            *(uint32_t*)&Ps[(qw + g + 8) * HST + c0] = pack_h2(p2, p3);
            oacc[nt][0] *= corr0;
            oacc[nt][1] *= corr0;
            oacc[nt][2] *= corr1;
            oacc[nt][3] *= corr1;
        }
        rsum0 += __shfl_xor_sync(0xFFFFFFFF, rsum0, 1);
        rsum0 += __shfl_xor_sync(0xFFFFFFFF, rsum0, 2);
        rsum1 += __shfl_xor_sync(0xFFFFFFFF, rsum1, 1);
        rsum1 += __shfl_xor_sync(0xFFFFFFFF, rsum1, 2);
        l0 = l0 * corr0 + rsum0;
        l1 = l1 * corr1 + rsum1;
        __syncwarp();

        // ---- O += P @ V ----
#pragma unroll
        for (int ks = 0; ks < 64; ks += 16) {
            uint32_t av[4];
            ldmatrix_x4(av, psBase + ((qw + lmARowOff) * HST + ks + lmAColOff) * 2);
#pragma unroll
            for (int p = 0; p < 4; p++) {
                uint32_t r[4];
                int col = p * 16 + lmVColOff;
                ldmatrix_x4_trans(r, vsBase + ((ks + lmVRow) * HST + col) * 2);
                mma_f16(oacc[2 * p],     av, r);
                mma_f16(oacc[2 * p + 1], av, r + 2);
            }
        }
        __syncthreads();
    }

    float invl0 = 1.0f / l0;
    float invl1 = 1.0f / l1;
    __half* ob0 = o + ((size_t)(b * SS + q0 + qw + g)) * DD + hh * HD;
    __half* ob1 = ob0 + (size_t)8 * DD;
#pragma unroll
    for (int nt = 0; nt < 8; nt++) {
        int c = nt * 8 + 2 * tg;
        *(uint32_t*)(ob0 + c) = pack_h2(oacc[nt][0] * invl0, oacc[nt][1] * invl0);
        *(uint32_t*)(ob1 + c) = pack_h2(oacc[nt][2] * invl1, oacc[nt][3] * invl1);
    }
}

// ---------------- driver -----------------------------------------------------
extern "C" void kernel_launch(void* const* d_in, const int* in_sizes, int n_in,
                              void* d_out, int out_size) {
    const float* x      = (const float*)d_in[0];
    const int*   vids   = (const int*)  d_in[1];
    const float* mask   = (const float*)d_in[2];
    const float* W_pe   = (const float*)d_in[3];
    const float* b_pe   = (const float*)d_in[4];
    const float* Wq     = (const float*)d_in[5];
    const float* bq     = (const float*)d_in[6];
    const float* Wk     = (const float*)d_in[7];
    const float* bk     = (const float*)d_in[8];
    const float* Wv     = (const float*)d_in[9];
    const float* bv     = (const float*)d_in[10];
    const float* Wo     = (const float*)d_in[11];
    const float* bo     = (const float*)d_in[12];
    const float* u_same = (const float*)d_in[13];
    const float* u_cross= (const float*)d_in[14];
    const float* g1     = (const float*)d_in[15];
    const float* be1    = (const float*)d_in[16];
    const float* W1     = (const float*)d_in[17];
    const float* b1f    = (const float*)d_in[18];
    const float* W2     = (const float*)d_in[19];
    const float* b2f    = (const float*)d_in[20];
    const float* g2     = (const float*)d_in[21];
    const float* be2    = (const float*)d_in[22];
    const float* Wh     = (const float*)d_in[23];
    const float* bh     = (const float*)d_in[24];
    float* out = (float*)d_out;

    float *ph, *pt, *pc, *ps;
    __half *phh, *pq, *pk, *pv, *po, *pff, *pxh, *pwh;
    cudaGetSymbolAddress((void**)&ph,  g_h);
    cudaGetSymbolAddress((void**)&pt,  g_t);
    cudaGetSymbolAddress((void**)&phh, g_hh);
    cudaGetSymbolAddress((void**)&pq,  g_qh);
    cudaGetSymbolAddress((void**)&pk,  g_kh);
    cudaGetSymbolAddress((void**)&pv,  g_vh);
    cudaGetSymbolAddress((void**)&po,  g_oh);
    cudaGetSymbolAddress((void**)&pff, g_ffh);
    cudaGetSymbolAddress((void**)&pxh, g_xh);
    cudaGetSymbolAddress((void**)&pwh, g_wh);
    cudaGetSymbolAddress((void**)&pc,  g_cos);
    cudaGetSymbolAddress((void**)&ps,  g_sin);

    static int smem_set = 0;
    if (!smem_set) {
        cudaFuncSetAttribute(attn4_kernel, cudaFuncAttributeMaxDynamicSharedMemorySize,
                             ATTN_DSMEM);
        smem_set = 1;
    }

    convert_kernel<<<(NX + TOTAL_W + 255) / 256, 256>>>(
        x, W_pe, Wq, Wk, Wv, Wo, W1, W2, pxh, pwh);
    rope_tables_kernel<<<(SS * 32 + 255) / 256, 256>>>(pc, ps);

    const __half* wpe = pwh + OFF_WPE;
    tgemm_bias<0, 0, 2><<<dim3(DD / 128, MM / 128), 256>>>(
        pxh, wpe, wpe, wpe, b_pe, b_pe, b_pe, ph, ph, ph, phh,
        pc, ps, MM, DD, PP, DD / 128);

    for (int l = 0; l < LL; l++) {
        const __half* Wql = pwh + OFF_WQ + (size_t)l * S_W;
        const __half* Wkl = pwh + OFF_WK + (size_t)l * S_W;
        const __half* Wvl = pwh + OFF_WV + (size_t)l * S_W;
        const __half* Wol = pwh + OFF_WO + (size_t)l * S_W;
        const __half* W1l = pwh + OFF_W1 + (size_t)l * S_W1;
        const __half* W2l = pwh + OFF_W2 + (size_t)l * S_W1;

        tgemm_bias<0, 1, 1><<<dim3(3 * (DD / 128), MM / 128), 256>>>(
            phh, Wql, Wkl, Wvl, bq + l * DD, bk + l * DD, bv + l * DD,
            pq, pk, pv, (__half*)0, pc, ps, MM, DD, DD, DD / 128);

        attn4_kernel<<<BB * HH * (SS / 64), 128, ATTN_DSMEM>>>(
            pq, pk, pv, vids, mask, u_same + l * HH, u_cross + l * HH, po);

        tgemm_bias<0, 0, 0><<<dim3(DD / 128, MM / 128), 256>>>(
            po, Wol, Wol, Wol, bo + l * DD, bo + l * DD, bo + l * DD,
            pt, pt, pt, (__half*)0, pc, ps, MM, DD, DD, DD / 128);
        add_ln_kernel<<<MM, 128>>>(ph, pt, g1 + l * DD, be1 + l * DD, phh);

        tgemm_bias<1, 0, 1><<<dim3(DF / 128, MM / 128), 256>>>(
            phh, W1l, W1l, W1l, b1f + l * DF, b1f + l * DF, b1f + l * DF,
            pff, pff, pff, (__half*)0, pc, ps, MM, DF, DD, DF / 128);
        tgemm_bias<0, 0, 0><<<dim3(DD / 128, MM / 128), 256>>>(
            pff, W2l, W2l, W2l, b2f + l * DD, b2f + l * DD, b2f + l * DD,
            pt, pt, pt, (__half*)0, pc, ps, MM, DD, DF, DD / 128);
        add_ln_kernel<<<MM, 128>>>(ph, pt, g2 + l * DD, be2 + l * DD, phh);
    }

    head_gemm_kernel<<<(MM * PP) / 256, 256>>>(ph, Wh, bh, out);
}